// round 1
// baseline (speedup 1.0000x reference)
#include <cuda_runtime.h>

// Problem dims (fixed for this problem instance)
#define Bz 8
#define Tz 1024
#define Dz 1024
#define Fz 4096
#define Mz (Bz * Tz)   // 8192 rows for all GEMMs

// ---------------- scratch (device globals: no allocations allowed) -----------
__device__ float g_R [(size_t)Mz * Dz];   // R pre-spike, then free
__device__ float g_K [(size_t)Mz * Dz];   // K pre-spike, then attn_out... reuse chain below
__device__ float g_V [(size_t)Mz * Dz];
__device__ float g_Y [(size_t)Mz * Dz];   // attn scan output y
__device__ float g_X1[(size_t)Mz * Dz];   // ln1 output
__device__ float g_H1[(size_t)Mz * Fz];   // fc1 pre-spike
__device__ float g_S1[(size_t)Mz * Fz];   // fc1 spikes

// ---------------- SGEMM: C[M,N] = A[M,K] * B[N,K]^T (+bias) -----------------
// BM=BN=128, BK=16, 256 threads, 8x8 per thread.
__global__ __launch_bounds__(256, 2)
void sgemm_nt(const float* __restrict__ A, const float* __restrict__ B,
              const float* __restrict__ bias, float* __restrict__ C,
              int M, int N, int K)
{
    __shared__ float As[16][128];
    __shared__ float Bs[16][128];

    const int tid = threadIdx.x;
    const int tx  = tid & 15;   // N direction (8 cols each)
    const int ty  = tid >> 4;   // M direction (8 rows each)

    const float* Ab = A + (size_t)blockIdx.y * 128 * K;
    const float* Bb = B + (size_t)blockIdx.x * 128 * K;

    float acc[8][8];
#pragma unroll
    for (int i = 0; i < 8; i++)
#pragma unroll
        for (int j = 0; j < 8; j++) acc[i][j] = 0.f;

    for (int k0 = 0; k0 < K; k0 += 16) {
#pragma unroll
        for (int u = 0; u < 2; u++) {
            int i4  = tid + u * 256;          // 512 float4 per tile
            int row = i4 >> 2;
            int c4  = (i4 & 3) << 2;
            float4 a = *reinterpret_cast<const float4*>(Ab + (size_t)row * K + k0 + c4);
            As[c4 + 0][row] = a.x; As[c4 + 1][row] = a.y;
            As[c4 + 2][row] = a.z; As[c4 + 3][row] = a.w;
            float4 b = *reinterpret_cast<const float4*>(Bb + (size_t)row * K + k0 + c4);
            Bs[c4 + 0][row] = b.x; Bs[c4 + 1][row] = b.y;
            Bs[c4 + 2][row] = b.z; Bs[c4 + 3][row] = b.w;
        }
        __syncthreads();
#pragma unroll
        for (int k = 0; k < 16; k++) {
            float ar[8], br[8];
            *reinterpret_cast<float4*>(&ar[0]) = *reinterpret_cast<const float4*>(&As[k][ty * 8]);
            *reinterpret_cast<float4*>(&ar[4]) = *reinterpret_cast<const float4*>(&As[k][ty * 8 + 4]);
            *reinterpret_cast<float4*>(&br[0]) = *reinterpret_cast<const float4*>(&Bs[k][tx * 8]);
            *reinterpret_cast<float4*>(&br[4]) = *reinterpret_cast<const float4*>(&Bs[k][tx * 8 + 4]);
#pragma unroll
            for (int i = 0; i < 8; i++)
#pragma unroll
                for (int j = 0; j < 8; j++)
                    acc[i][j] = fmaf(ar[i], br[j], acc[i][j]);
        }
        __syncthreads();
    }

    float bv[8];
#pragma unroll
    for (int j = 0; j < 8; j++)
        bv[j] = bias ? bias[blockIdx.x * 128 + tx * 8 + j] : 0.f;

#pragma unroll
    for (int i = 0; i < 8; i++) {
        size_t r = (size_t)blockIdx.y * 128 + ty * 8 + i;
        float* Cp = C + r * N + blockIdx.x * 128 + tx * 8;
        float4 o0 = make_float4(acc[i][0] + bv[0], acc[i][1] + bv[1],
                                acc[i][2] + bv[2], acc[i][3] + bv[3]);
        float4 o1 = make_float4(acc[i][4] + bv[4], acc[i][5] + bv[5],
                                acc[i][6] + bv[6], acc[i][7] + bv[7]);
        *reinterpret_cast<float4*>(Cp)     = o0;
        *reinterpret_cast<float4*>(Cp + 4) = o1;
    }
}

// ---------------- attention RWKV scan: thread per (b,d), sequential in T ----
__global__ void attn_scan(const float* __restrict__ R, const float* __restrict__ Kx,
                          const float* __restrict__ Vx, float* __restrict__ Y)
{
    int idx = blockIdx.x * blockDim.x + threadIdx.x;   // 0 .. B*D-1
    size_t base = ((size_t)(idx >> 10)) * Tz * Dz + (idx & 1023);
    float vr = 0.f, vk = 0.f, vv = 0.f, h = 0.f;
#pragma unroll 4
    for (int t = 0; t < Tz; t++) {
        size_t off = base + (size_t)t * Dz;
        float ri = R[off], ki = Kx[off], vi = Vx[off];

        vr += (ri - vr) * 0.5f;
        float rs = (vr >= 1.0f) ? 1.f : 0.f;
        if (rs != 0.f) vr = 0.f;

        vk += (ki - vk) * 0.5f;
        float ks = (vk >= 1.0f) ? 1.f : 0.f;
        if (ks != 0.f) vk = 0.f;

        vv += (vi - vv) * 0.5f;
        float vs = (vv >= 1.0f) ? 1.f : 0.f;
        if (vs != 0.f) vv = 0.f;

        h = h * 0.9f + ks * vs;
        Y[off] = rs * h;
    }
}

// ---------------- LIF scan (fc1 / fc2): thread per (b,channel) --------------
__global__ void lif_scan_k(const float* __restrict__ X, float* __restrict__ S, int width)
{
    int idx = blockIdx.x * blockDim.x + threadIdx.x;   // 0 .. B*width-1
    int b = idx / width;
    int f = idx - b * width;
    size_t base = (size_t)b * Tz * width + f;
    float v = 0.f;
#pragma unroll 8
    for (int t = 0; t < Tz; t++) {
        size_t off = base + (size_t)t * width;
        float x = X[off];
        v += (x - v) * 0.5f;
        float s = (v >= 1.0f) ? 1.f : 0.f;
        if (s != 0.f) v = 0.f;
        S[off] = s;
    }
}

// ---------------- fused residual-add + LayerNorm (block per row, D=1024) ----
__global__ void add_ln(const float* __restrict__ A, const float* __restrict__ Bv,
                       const float* __restrict__ g, const float* __restrict__ beta,
                       float* __restrict__ O)
{
    __shared__ float sm[16];
    int row = blockIdx.x;
    int tid = threadIdx.x;           // 256 threads, 4 elems each
    size_t base = (size_t)row * Dz;
    int c = tid * 4;

    float4 a = *reinterpret_cast<const float4*>(A  + base + c);
    float4 b = *reinterpret_cast<const float4*>(Bv + base + c);
    float x0 = a.x + b.x, x1 = a.y + b.y, x2 = a.z + b.z, x3 = a.w + b.w;

    float s  = x0 + x1 + x2 + x3;
    float ss = x0 * x0 + x1 * x1 + x2 * x2 + x3 * x3;
#pragma unroll
    for (int o = 16; o > 0; o >>= 1) {
        s  += __shfl_xor_sync(0xFFFFFFFFu, s,  o);
        ss += __shfl_xor_sync(0xFFFFFFFFu, ss, o);
    }
    int wid = tid >> 5, lane = tid & 31;
    if (lane == 0) { sm[wid] = s; sm[wid + 8] = ss; }
    __syncthreads();
    if (wid == 0) {
        float s2  = (lane < 8) ? sm[lane]     : 0.f;
        float ss2 = (lane < 8) ? sm[lane + 8] : 0.f;
#pragma unroll
        for (int o = 4; o > 0; o >>= 1) {
            s2  += __shfl_xor_sync(0xFFFFFFFFu, s2,  o);
            ss2 += __shfl_xor_sync(0xFFFFFFFFu, ss2, o);
        }
        if (lane == 0) { sm[0] = s2; sm[1] = ss2; }
    }
    __syncthreads();

    float mu  = sm[0] * (1.f / 1024.f);
    float var = sm[1] * (1.f / 1024.f) - mu * mu;
    float inv = rsqrtf(var + 1e-5f);

    float4 gg = *reinterpret_cast<const float4*>(g    + c);
    float4 bb = *reinterpret_cast<const float4*>(beta + c);
    float4 o;
    o.x = (x0 - mu) * inv * gg.x + bb.x;
    o.y = (x1 - mu) * inv * gg.y + bb.y;
    o.z = (x2 - mu) * inv * gg.z + bb.z;
    o.w = (x3 - mu) * inv * gg.w + bb.w;
    *reinterpret_cast<float4*>(O + base + c) = o;
}

// ---------------------------------------------------------------------------
extern "C" void kernel_launch(void* const* d_in, const int* in_sizes, int n_in,
                              void* d_out, int out_size)
{
    const float* x    = (const float*)d_in[0];
    const float* Wr   = (const float*)d_in[1];
    const float* Wk   = (const float*)d_in[2];
    const float* Wv   = (const float*)d_in[3];
    const float* Wo   = (const float*)d_in[4];
    const float* W1   = (const float*)d_in[5];
    const float* b1   = (const float*)d_in[6];
    const float* W2   = (const float*)d_in[7];
    const float* b2   = (const float*)d_in[8];
    const float* ln1g = (const float*)d_in[9];
    const float* ln1b = (const float*)d_in[10];
    const float* ln2g = (const float*)d_in[11];
    const float* ln2b = (const float*)d_in[12];
    float* out = (float*)d_out;

    float *pR, *pK, *pV, *pY, *pX1, *pH1, *pS1;
    cudaGetSymbolAddress((void**)&pR,  g_R);
    cudaGetSymbolAddress((void**)&pK,  g_K);
    cudaGetSymbolAddress((void**)&pV,  g_V);
    cudaGetSymbolAddress((void**)&pY,  g_Y);
    cudaGetSymbolAddress((void**)&pX1, g_X1);
    cudaGetSymbolAddress((void**)&pH1, g_H1);
    cudaGetSymbolAddress((void**)&pS1, g_S1);

    dim3 blk(256);
    dim3 g_dd(Dz / 128, Mz / 128);   // N=1024 GEMMs
    dim3 g_df(Fz / 128, Mz / 128);   // N=4096 GEMM

    // 1-3: R/K/V projections
    sgemm_nt<<<g_dd, blk>>>(x, Wr, nullptr, pR, Mz, Dz, Dz);
    sgemm_nt<<<g_dd, blk>>>(x, Wk, nullptr, pK, Mz, Dz, Dz);
    sgemm_nt<<<g_dd, blk>>>(x, Wv, nullptr, pV, Mz, Dz, Dz);

    // 4: RWKV/LIF attention scan -> y
    attn_scan<<<(Bz * Dz) / 256, blk>>>(pR, pK, pV, pY);

    // 5: output projection -> attn_out (reuse g_R)
    sgemm_nt<<<g_dd, blk>>>(pY, Wo, nullptr, pR, Mz, Dz, Dz);

    // 6: x1 = LN(x + attn_out)
    add_ln<<<Mz, blk>>>(x, pR, ln1g, ln1b, pX1);

    // 7: h1 = x1 @ W1^T + b1
    sgemm_nt<<<g_df, blk>>>(pX1, W1, b1, pH1, Mz, Fz, Dz);

    // 8: s1 = lif_scan(h1)
    lif_scan_k<<<(Bz * Fz) / 256, blk>>>(pH1, pS1, Fz);

    // 9: h2 = s1 @ W2^T + b2 (reuse g_K)
    sgemm_nt<<<g_dd, blk>>>(pS1, W2, b2, pK, Mz, Dz, Fz);

    // 10: ffn_out = lif_scan(h2) (reuse g_V)
    lif_scan_k<<<(Bz * Dz) / 256, blk>>>(pK, pV, Dz);

    // 11: out = LN(x1 + ffn_out)
    add_ln<<<Mz, blk>>>(pX1, pV, ln2g, ln2b, out);
}

// round 3
// speedup vs baseline: 2.1469x; 2.1469x over previous
#include <cuda_runtime.h>
#include <cuda_bf16.h>
#include <cstdint>

#define Bz 8
#define Tz 1024
#define Dz 1024
#define Fz 4096
#define Mz (Bz * Tz)   // 8192

// ---------------------------------------------------------------------------
// Device scratch (no allocations allowed)
// ---------------------------------------------------------------------------
__device__ float g_R  [(size_t)Mz * Dz];
__device__ float g_Kp [(size_t)Mz * Dz];
__device__ float g_V  [(size_t)Mz * Dz];
__device__ float g_AO [(size_t)Mz * Dz];
__device__ float g_X1 [(size_t)Mz * Dz];
__device__ float g_H2 [(size_t)Mz * Dz];
__device__ float g_FFN[(size_t)Mz * Dz];
__device__ float g_H1 [(size_t)Mz * Fz];

__device__ __nv_bfloat16 g_xh [(size_t)Mz * Dz];
__device__ __nv_bfloat16 g_xl [(size_t)Mz * Dz];
__device__ __nv_bfloat16 g_yh [(size_t)Mz * Dz];
__device__ __nv_bfloat16 g_yl [(size_t)Mz * Dz];
__device__ __nv_bfloat16 g_x1h[(size_t)Mz * Dz];
__device__ __nv_bfloat16 g_x1l[(size_t)Mz * Dz];
__device__ __nv_bfloat16 g_s1 [(size_t)Mz * Fz];

#define NWELEM (4u * 1048576u + 2u * 4194304u)
__device__ __nv_bfloat16 g_wh[NWELEM];
__device__ __nv_bfloat16 g_wl[NWELEM];

#define OFF_WR 0u
#define OFF_WK 1048576u
#define OFF_WV 2097152u
#define OFF_WO 3145728u
#define OFF_W1 4194304u
#define OFF_W2 8388608u

// ---------------------------------------------------------------------------
// helpers
// ---------------------------------------------------------------------------
__device__ __forceinline__ uint32_t smem_u32(const void* p) {
    uint32_t a;
    asm("{ .reg .u64 t; cvta.to.shared.u64 t, %1; cvt.u32.u64 %0, t; }"
        : "=r"(a) : "l"(p));
    return a;
}

#define LDSM_X4(r0, r1, r2, r3, addr) \
    asm volatile("ldmatrix.sync.aligned.m8n8.x4.shared.b16 {%0,%1,%2,%3}, [%4];" \
                 : "=r"(r0), "=r"(r1), "=r"(r2), "=r"(r3) : "r"(addr))

#define MMA16816(d, a, b0_, b1_) \
    asm volatile("mma.sync.aligned.m16n8k16.row.col.f32.bf16.bf16.f32 " \
                 "{%0,%1,%2,%3},{%4,%5,%6,%7},{%8,%9},{%0,%1,%2,%3};" \
                 : "+f"((d)[0]), "+f"((d)[1]), "+f"((d)[2]), "+f"((d)[3]) \
                 : "r"((a)[0]), "r"((a)[1]), "r"((a)[2]), "r"((a)[3]), \
                   "r"(b0_), "r"(b1_))

// ---------------------------------------------------------------------------
// Split-bf16 mma.sync GEMM: C[M,N] = A[M,K] * B[N,K]^T (+bias), fp32 out.
// TERMS==3: Ahi*Bhi + Alo*Bhi + Ahi*Blo.  TERMS==2: Ahi*Bhi + Ahi*Blo.
// BM=BN=128, BK=32, 256 threads (8 warps, 4x2, warp tile 32x64),
// 3-stage cp.async pipeline, 80B-padded smem rows (conflict-free ldmatrix).
// ---------------------------------------------------------------------------
template <int TERMS>
__global__ __launch_bounds__(256, 1)
void mma_gemm(const __nv_bfloat16* __restrict__ Ah, const __nv_bfloat16* __restrict__ Al,
              const __nv_bfloat16* __restrict__ Bh, const __nv_bfloat16* __restrict__ Bl,
              const float* __restrict__ bias, float* __restrict__ C,
              int N, int K)
{
    constexpr int S      = 3;
    constexpr int NA     = (TERMS == 3) ? 2 : 1;      // # A matrices
    constexpr int NMAT   = NA + 2;                    // + Bhi, Blo
    constexpr int MATB   = 128 * 80;                  // bytes per matrix tile (128 x 40 bf16)
    constexpr int STAGEB = NMAT * MATB;
    constexpr int NCHUNK = NMAT * 2;                  // 16B chunks per thread per stage

    extern __shared__ __align__(16) char smem[];
    const uint32_t sb = smem_u32(smem);

    const int tid  = threadIdx.x;
    const int lane = tid & 31;
    const int warp = tid >> 5;
    const int m0w  = (warp >> 1) * 32;
    const int n0w  = (warp & 1) * 64;
    const int mBlk = blockIdx.y * 128;
    const int nBlk = blockIdx.x * 128;

    const __nv_bfloat16* srcs[4];
    srcs[0] = Ah;
    if (TERMS == 3) { srcs[1] = Al; srcs[2] = Bh; srcs[3] = Bl; }
    else            { srcs[1] = Bh; srcs[2] = Bl; srcs[3] = Bl; }

    const __nv_bfloat16* sp[NCHUNK];
    uint32_t dof[NCHUNK];
#pragma unroll
    for (int i = 0; i < NCHUNK; i++) {
        int c   = i * 256 + tid;
        int mat = c >> 9;             // 512 chunks per matrix
        int r   = (c >> 2) & 127;
        int c16 = c & 3;
        int rowbase = (mat < NA) ? mBlk : nBlk;
        sp[i]  = srcs[mat] + (size_t)(rowbase + r) * K + c16 * 8;
        dof[i] = mat * MATB + r * 80 + c16 * 16;
    }

    const int NT = K / 32;

    // prologue: stages 0,1
#pragma unroll
    for (int s = 0; s < S - 1; s++) {
        uint32_t base = sb + s * STAGEB;
#pragma unroll
        for (int i = 0; i < NCHUNK; i++) {
            unsigned long long g =
                (unsigned long long)__cvta_generic_to_global(sp[i] + s * 32);
            asm volatile("cp.async.cg.shared.global [%0], [%1], 16;"
                         :: "r"(base + dof[i]), "l"(g));
        }
        asm volatile("cp.async.commit_group;");
    }

    float acc[2][8][4];
#pragma unroll
    for (int i = 0; i < 2; i++)
#pragma unroll
        for (int j = 0; j < 8; j++)
#pragma unroll
            for (int k = 0; k < 4; k++) acc[i][j][k] = 0.f;

    const uint32_t aoff = (uint32_t)((m0w + (lane & 15)) * 80 + (lane >> 4) * 16);
    const uint32_t boff = (uint32_t)((n0w + ((lane >> 4) & 1) * 8 + (lane & 7)) * 80
                                     + ((lane >> 3) & 1) * 16);
    const uint32_t mAhi = 0;
    const uint32_t mAlo = MATB;                 // only valid if TERMS==3
    const uint32_t mBhi = NA * MATB;
    const uint32_t mBlo = (NA + 1) * MATB;

    for (int kt = 0; kt < NT; kt++) {
        asm volatile("cp.async.wait_group 1;" ::: "memory");
        __syncthreads();
        const uint32_t st = sb + (kt % S) * STAGEB;

#pragma unroll
        for (int kk = 0; kk < 2; kk++) {
            const uint32_t kb = kk * 32;

            uint32_t ah[2][4];
#pragma unroll
            for (int mt = 0; mt < 2; mt++)
                LDSM_X4(ah[mt][0], ah[mt][1], ah[mt][2], ah[mt][3],
                        st + mAhi + aoff + mt * 1280 + kb);

            uint32_t bh[4][4];
#pragma unroll
            for (int q = 0; q < 4; q++)
                LDSM_X4(bh[q][0], bh[q][1], bh[q][2], bh[q][3],
                        st + mBhi + boff + q * 1280 + kb);

#pragma unroll
            for (int mt = 0; mt < 2; mt++)
#pragma unroll
                for (int q = 0; q < 4; q++) {
                    MMA16816(acc[mt][2 * q],     ah[mt], bh[q][0], bh[q][1]);
                    MMA16816(acc[mt][2 * q + 1], ah[mt], bh[q][2], bh[q][3]);
                }

            if (TERMS == 3) {
                uint32_t al[2][4];
#pragma unroll
                for (int mt = 0; mt < 2; mt++)
                    LDSM_X4(al[mt][0], al[mt][1], al[mt][2], al[mt][3],
                            st + mAlo + aoff + mt * 1280 + kb);
#pragma unroll
                for (int mt = 0; mt < 2; mt++)
#pragma unroll
                    for (int q = 0; q < 4; q++) {
                        MMA16816(acc[mt][2 * q],     al[mt], bh[q][0], bh[q][1]);
                        MMA16816(acc[mt][2 * q + 1], al[mt], bh[q][2], bh[q][3]);
                    }
            }

            uint32_t bl[4][4];
#pragma unroll
            for (int q = 0; q < 4; q++)
                LDSM_X4(bl[q][0], bl[q][1], bl[q][2], bl[q][3],
                        st + mBlo + boff + q * 1280 + kb);
#pragma unroll
            for (int mt = 0; mt < 2; mt++)
#pragma unroll
                for (int q = 0; q < 4; q++) {
                    MMA16816(acc[mt][2 * q],     ah[mt], bl[q][0], bl[q][1]);
                    MMA16816(acc[mt][2 * q + 1], ah[mt], bl[q][2], bl[q][3]);
                }
        }
        __syncthreads();

        int nxt = kt + S - 1;
        if (nxt < NT) {
            uint32_t base = sb + (nxt % S) * STAGEB;
#pragma unroll
            for (int i = 0; i < NCHUNK; i++) {
                unsigned long long g =
                    (unsigned long long)__cvta_generic_to_global(sp[i] + nxt * 32);
                asm volatile("cp.async.cg.shared.global [%0], [%1], 16;"
                             :: "r"(base + dof[i]), "l"(g));
            }
        }
        asm volatile("cp.async.commit_group;");
    }

    // epilogue
    const int cbase = nBlk + n0w + 2 * (lane & 3);
    const int rbase = mBlk + m0w + (lane >> 2);
#pragma unroll
    for (int mt = 0; mt < 2; mt++) {
#pragma unroll
        for (int nt = 0; nt < 8; nt++) {
            int col = cbase + nt * 8;
            float b0 = 0.f, b1 = 0.f;
            if (bias) { b0 = bias[col]; b1 = bias[col + 1]; }
            int r0 = rbase + mt * 16;
            float2 v0 = make_float2(acc[mt][nt][0] + b0, acc[mt][nt][1] + b1);
            float2 v1 = make_float2(acc[mt][nt][2] + b0, acc[mt][nt][3] + b1);
            *reinterpret_cast<float2*>(C + (size_t)r0 * N + col)       = v0;
            *reinterpret_cast<float2*>(C + (size_t)(r0 + 8) * N + col) = v1;
        }
    }
}

// ---------------------------------------------------------------------------
// fp32 -> bf16 hi/lo split
// ---------------------------------------------------------------------------
__global__ void split_k(const float* __restrict__ x, __nv_bfloat16* __restrict__ hi,
                        __nv_bfloat16* __restrict__ lo, int n4)
{
    for (int i = blockIdx.x * blockDim.x + threadIdx.x; i < n4;
         i += gridDim.x * blockDim.x) {
        float4 v = reinterpret_cast<const float4*>(x)[i];
        __nv_bfloat16 h0 = __float2bfloat16(v.x);
        __nv_bfloat16 h1 = __float2bfloat16(v.y);
        __nv_bfloat16 h2 = __float2bfloat16(v.z);
        __nv_bfloat16 h3 = __float2bfloat16(v.w);
        reinterpret_cast<__nv_bfloat162*>(hi)[2 * i]     = __nv_bfloat162(h0, h1);
        reinterpret_cast<__nv_bfloat162*>(hi)[2 * i + 1] = __nv_bfloat162(h2, h3);
        __nv_bfloat16 l0 = __float2bfloat16(v.x - __bfloat162float(h0));
        __nv_bfloat16 l1 = __float2bfloat16(v.y - __bfloat162float(h1));
        __nv_bfloat16 l2 = __float2bfloat16(v.z - __bfloat162float(h2));
        __nv_bfloat16 l3 = __float2bfloat16(v.w - __bfloat162float(h3));
        reinterpret_cast<__nv_bfloat162*>(lo)[2 * i]     = __nv_bfloat162(l0, l1);
        reinterpret_cast<__nv_bfloat162*>(lo)[2 * i + 1] = __nv_bfloat162(l2, l3);
    }
}

// ---------------------------------------------------------------------------
// RWKV attention scan: thread per (b,d); writes y as bf16 hi/lo
// ---------------------------------------------------------------------------
__global__ void attn_scan(const float* __restrict__ R, const float* __restrict__ Kx,
                          const float* __restrict__ Vx,
                          __nv_bfloat16* __restrict__ Yh, __nv_bfloat16* __restrict__ Yl)
{
    int idx = blockIdx.x * blockDim.x + threadIdx.x;
    size_t base = ((size_t)(idx >> 10)) * Tz * Dz + (idx & 1023);
    float vr = 0.f, vk = 0.f, vv = 0.f, h = 0.f;
#pragma unroll 4
    for (int t = 0; t < Tz; t++) {
        size_t off = base + (size_t)t * Dz;
        float ri = R[off], ki = Kx[off], vi = Vx[off];

        vr += (ri - vr) * 0.5f;
        float rs = (vr >= 1.0f) ? 1.f : 0.f;
        if (rs != 0.f) vr = 0.f;

        vk += (ki - vk) * 0.5f;
        float ks = (vk >= 1.0f) ? 1.f : 0.f;
        if (ks != 0.f) vk = 0.f;

        vv += (vi - vv) * 0.5f;
        float vs = (vv >= 1.0f) ? 1.f : 0.f;
        if (vs != 0.f) vv = 0.f;

        h = h * 0.9f + ks * vs;
        float y = rs * h;
        __nv_bfloat16 yh = __float2bfloat16(y);
        Yh[off] = yh;
        Yl[off] = __float2bfloat16(y - __bfloat162float(yh));
    }
}

// ---------------------------------------------------------------------------
// LIF scans
// ---------------------------------------------------------------------------
__global__ void lif_scan_bf16(const float* __restrict__ X, __nv_bfloat16* __restrict__ S,
                              int width)
{
    int idx = blockIdx.x * blockDim.x + threadIdx.x;
    int b = idx / width;
    int f = idx - b * width;
    size_t base = (size_t)b * Tz * width + f;
    float v = 0.f;
#pragma unroll 8
    for (int t = 0; t < Tz; t++) {
        size_t off = base + (size_t)t * width;
        float x = X[off];
        v += (x - v) * 0.5f;
        float s = (v >= 1.0f) ? 1.f : 0.f;
        if (s != 0.f) v = 0.f;
        S[off] = __float2bfloat16(s);   // exact: s in {0,1}
    }
}

__global__ void lif_scan_f32(const float* __restrict__ X, float* __restrict__ S, int width)
{
    int idx = blockIdx.x * blockDim.x + threadIdx.x;
    int b = idx / width;
    int f = idx - b * width;
    size_t base = (size_t)b * Tz * width + f;
    float v = 0.f;
#pragma unroll 8
    for (int t = 0; t < Tz; t++) {
        size_t off = base + (size_t)t * width;
        float x = X[off];
        v += (x - v) * 0.5f;
        float s = (v >= 1.0f) ? 1.f : 0.f;
        if (s != 0.f) v = 0.f;
        S[off] = s;
    }
}

// ---------------------------------------------------------------------------
// fused residual add + LayerNorm (block per row, D=1024, 256 threads)
// ---------------------------------------------------------------------------
template <bool SPLIT>
__global__ void add_ln(const float* __restrict__ A, const float* __restrict__ Bv,
                       const float* __restrict__ g, const float* __restrict__ beta,
                       float* __restrict__ O,
                       __nv_bfloat16* __restrict__ Oh, __nv_bfloat16* __restrict__ Ol)
{
    __shared__ float sm[16];
    int row = blockIdx.x;
    int tid = threadIdx.x;
    size_t base = (size_t)row * Dz;
    int c = tid * 4;

    float4 a = *reinterpret_cast<const float4*>(A  + base + c);
    float4 b = *reinterpret_cast<const float4*>(Bv + base + c);
    float x0 = a.x + b.x, x1 = a.y + b.y, x2 = a.z + b.z, x3 = a.w + b.w;

    float s  = x0 + x1 + x2 + x3;
    float ss = x0 * x0 + x1 * x1 + x2 * x2 + x3 * x3;
#pragma unroll
    for (int o = 16; o > 0; o >>= 1) {
        s  += __shfl_xor_sync(0xFFFFFFFFu, s,  o);
        ss += __shfl_xor_sync(0xFFFFFFFFu, ss, o);
    }
    int wid = tid >> 5, lane = tid & 31;
    if (lane == 0) { sm[wid] = s; sm[wid + 8] = ss; }
    __syncthreads();
    if (wid == 0) {
        float s2  = (lane < 8) ? sm[lane]     : 0.f;
        float ss2 = (lane < 8) ? sm[lane + 8] : 0.f;
#pragma unroll
        for (int o = 4; o > 0; o >>= 1) {
            s2  += __shfl_xor_sync(0xFFFFFFFFu, s2,  o);
            ss2 += __shfl_xor_sync(0xFFFFFFFFu, ss2, o);
        }
        if (lane == 0) { sm[0] = s2; sm[1] = ss2; }
    }
    __syncthreads();

    float mu  = sm[0] * (1.f / 1024.f);
    float var = sm[1] * (1.f / 1024.f) - mu * mu;
    float inv = rsqrtf(var + 1e-5f);

    float4 gg = *reinterpret_cast<const float4*>(g    + c);
    float4 bb = *reinterpret_cast<const float4*>(beta + c);
    float4 o;
    o.x = (x0 - mu) * inv * gg.x + bb.x;
    o.y = (x1 - mu) * inv * gg.y + bb.y;
    o.z = (x2 - mu) * inv * gg.z + bb.z;
    o.w = (x3 - mu) * inv * gg.w + bb.w;
    *reinterpret_cast<float4*>(O + base + c) = o;

    if (SPLIT) {
        __nv_bfloat16 h0 = __float2bfloat16(o.x);
        __nv_bfloat16 h1 = __float2bfloat16(o.y);
        __nv_bfloat16 h2 = __float2bfloat16(o.z);
        __nv_bfloat16 h3 = __float2bfloat16(o.w);
        size_t i2 = (base + c) >> 1;
        reinterpret_cast<__nv_bfloat162*>(Oh)[i2]     = __nv_bfloat162(h0, h1);
        reinterpret_cast<__nv_bfloat162*>(Oh)[i2 + 1] = __nv_bfloat162(h2, h3);
        __nv_bfloat16 l0 = __float2bfloat16(o.x - __bfloat162float(h0));
        __nv_bfloat16 l1 = __float2bfloat16(o.y - __bfloat162float(h1));
        __nv_bfloat16 l2 = __float2bfloat16(o.z - __bfloat162float(h2));
        __nv_bfloat16 l3 = __float2bfloat16(o.w - __bfloat162float(h3));
        reinterpret_cast<__nv_bfloat162*>(Ol)[i2]     = __nv_bfloat162(l0, l1);
        reinterpret_cast<__nv_bfloat162*>(Ol)[i2 + 1] = __nv_bfloat162(l2, l3);
    }
}

// ---------------------------------------------------------------------------
// Host side
// ---------------------------------------------------------------------------
static void launch3(const __nv_bfloat16* Ah, const __nv_bfloat16* Al,
                    const __nv_bfloat16* Bh, const __nv_bfloat16* Bl,
                    const float* bias, float* C, int M, int N, int K)
{
    const int SMEM = 3 * 4 * 10240;   // 122880
    cudaFuncSetAttribute(mma_gemm<3>, cudaFuncAttributeMaxDynamicSharedMemorySize, SMEM);
    mma_gemm<3><<<dim3(N / 128, M / 128), 256, SMEM>>>(Ah, Al, Bh, Bl, bias, C, N, K);
}

static void launch2(const __nv_bfloat16* Ah,
                    const __nv_bfloat16* Bh, const __nv_bfloat16* Bl,
                    const float* bias, float* C, int M, int N, int K)
{
    const int SMEM = 3 * 3 * 10240;   // 92160
    cudaFuncSetAttribute(mma_gemm<2>, cudaFuncAttributeMaxDynamicSharedMemorySize, SMEM);
    mma_gemm<2><<<dim3(N / 128, M / 128), 256, SMEM>>>(Ah, Ah, Bh, Bl, bias, C, N, K);
}

extern "C" void kernel_launch(void* const* d_in, const int* in_sizes, int n_in,
                              void* d_out, int out_size)
{
    const float* x    = (const float*)d_in[0];
    const float* Wr   = (const float*)d_in[1];
    const float* Wk   = (const float*)d_in[2];
    const float* Wv   = (const float*)d_in[3];
    const float* Wo   = (const float*)d_in[4];
    const float* W1   = (const float*)d_in[5];
    const float* b1   = (const float*)d_in[6];
    const float* W2   = (const float*)d_in[7];
    const float* b2   = (const float*)d_in[8];
    const float* ln1g = (const float*)d_in[9];
    const float* ln1b = (const float*)d_in[10];
    const float* ln2g = (const float*)d_in[11];
    const float* ln2b = (const float*)d_in[12];
    float* out = (float*)d_out;

    float *pR, *pK, *pV, *pAO, *pX1, *pH1, *pH2, *pFFN;
    __nv_bfloat16 *pxh, *pxl, *pyh, *pyl, *px1h, *px1l, *ps1, *pwh, *pwl;
    cudaGetSymbolAddress((void**)&pR,   g_R);
    cudaGetSymbolAddress((void**)&pK,   g_Kp);
    cudaGetSymbolAddress((void**)&pV,   g_V);
    cudaGetSymbolAddress((void**)&pAO,  g_AO);
    cudaGetSymbolAddress((void**)&pX1,  g_X1);
    cudaGetSymbolAddress((void**)&pH1,  g_H1);
    cudaGetSymbolAddress((void**)&pH2,  g_H2);
    cudaGetSymbolAddress((void**)&pFFN, g_FFN);
    cudaGetSymbolAddress((void**)&pxh,  g_xh);
    cudaGetSymbolAddress((void**)&pxl,  g_xl);
    cudaGetSymbolAddress((void**)&pyh,  g_yh);
    cudaGetSymbolAddress((void**)&pyl,  g_yl);
    cudaGetSymbolAddress((void**)&px1h, g_x1h);
    cudaGetSymbolAddress((void**)&px1l, g_x1l);
    cudaGetSymbolAddress((void**)&ps1,  g_s1);
    cudaGetSymbolAddress((void**)&pwh,  g_wh);
    cudaGetSymbolAddress((void**)&pwl,  g_wl);

    // 1) splits: input x + all 6 weight matrices
    split_k<<<1024, 256>>>(x,  pxh, pxl, (Mz * Dz) / 4);
    split_k<<<512,  256>>>(Wr, pwh + OFF_WR, pwl + OFF_WR, (Dz * Dz) / 4);
    split_k<<<512,  256>>>(Wk, pwh + OFF_WK, pwl + OFF_WK, (Dz * Dz) / 4);
    split_k<<<512,  256>>>(Wv, pwh + OFF_WV, pwl + OFF_WV, (Dz * Dz) / 4);
    split_k<<<512,  256>>>(Wo, pwh + OFF_WO, pwl + OFF_WO, (Dz * Dz) / 4);
    split_k<<<1024, 256>>>(W1, pwh + OFF_W1, pwl + OFF_W1, (Fz * Dz) / 4);
    split_k<<<1024, 256>>>(W2, pwh + OFF_W2, pwl + OFF_W2, (Dz * Fz) / 4);

    // 2) R/K/V projections (3-term split bf16 mma.sync, fp32 accumulate)
    launch3(pxh, pxl, pwh + OFF_WR, pwl + OFF_WR, nullptr, pR, Mz, Dz, Dz);
    launch3(pxh, pxl, pwh + OFF_WK, pwl + OFF_WK, nullptr, pK, Mz, Dz, Dz);
    launch3(pxh, pxl, pwh + OFF_WV, pwl + OFF_WV, nullptr, pV, Mz, Dz, Dz);

    // 3) RWKV attention scan -> y (bf16 hi/lo)
    attn_scan<<<(Bz * Dz) / 64, 64>>>(pR, pK, pV, pyh, pyl);

    // 4) output projection
    launch3(pyh, pyl, pwh + OFF_WO, pwl + OFF_WO, nullptr, pAO, Mz, Dz, Dz);

    // 5) x1 = LN(x + attn_out), plus bf16 hi/lo
    add_ln<true><<<Mz, 256>>>(x, pAO, ln1g, ln1b, pX1, px1h, px1l);

    // 6) h1 = x1 @ W1^T + b1
    launch3(px1h, px1l, pwh + OFF_W1, pwl + OFF_W1, b1, pH1, Mz, Fz, Dz);

    // 7) s1 = LIF(h1), spikes exact in bf16
    lif_scan_bf16<<<(Bz * Fz) / 64, 64>>>(pH1, ps1, Fz);

    // 8) h2 = s1 @ W2^T + b2  (2-term: s1 is bf16-exact)
    launch2(ps1, pwh + OFF_W2, pwl + OFF_W2, b2, pH2, Mz, Dz, Fz);

    // 9) ffn_out = LIF(h2)
    lif_scan_f32<<<(Bz * Dz) / 64, 64>>>(pH2, pFFN, Dz);

    // 10) out = LN(x1 + ffn_out)
    add_ln<false><<<Mz, 256>>>(pX1, pFFN, ln2g, ln2b, out, nullptr, nullptr);
}

// round 4
// speedup vs baseline: 2.7571x; 1.2842x over previous
#include <cuda_runtime.h>
#include <cuda_bf16.h>
#include <cstdint>

#define Bz 8
#define Tz 1024
#define Dz 1024
#define Fz 4096
#define Mz (Bz * Tz)   // 8192

// ---------------------------------------------------------------------------
// Device scratch (no allocations allowed)
// ---------------------------------------------------------------------------
__device__ float g_RKV[(size_t)Mz * 3 * Dz];   // fused R|K|V, row stride 3072
__device__ float g_AO [(size_t)Mz * Dz];
__device__ float g_X1 [(size_t)Mz * Dz];
__device__ float g_H2 [(size_t)Mz * Dz];
__device__ float g_FFN[(size_t)Mz * Dz];
__device__ float g_H1 [(size_t)Mz * Fz];

__device__ __nv_bfloat16 g_xh [(size_t)Mz * Dz];
__device__ __nv_bfloat16 g_xl [(size_t)Mz * Dz];
__device__ __nv_bfloat16 g_yh [(size_t)Mz * Dz];
__device__ __nv_bfloat16 g_yl [(size_t)Mz * Dz];
__device__ __nv_bfloat16 g_x1h[(size_t)Mz * Dz];
__device__ __nv_bfloat16 g_x1l[(size_t)Mz * Dz];
__device__ __nv_bfloat16 g_s1 [(size_t)Mz * Fz];

#define NWELEM (4u * 1048576u + 2u * 4194304u)
__device__ __nv_bfloat16 g_wh[NWELEM];
__device__ __nv_bfloat16 g_wl[NWELEM];

#define OFF_WR 0u
#define OFF_WK 1048576u
#define OFF_WV 2097152u
#define OFF_WO 3145728u
#define OFF_W1 4194304u
#define OFF_W2 8388608u

// ---------------------------------------------------------------------------
// helpers
// ---------------------------------------------------------------------------
__device__ __forceinline__ uint32_t smem_u32(const void* p) {
    uint32_t a;
    asm("{ .reg .u64 t; cvta.to.shared.u64 t, %1; cvt.u32.u64 %0, t; }"
        : "=r"(a) : "l"(p));
    return a;
}

#define LDSM_X4(r0, r1, r2, r3, addr) \
    asm volatile("ldmatrix.sync.aligned.m8n8.x4.shared.b16 {%0,%1,%2,%3}, [%4];" \
                 : "=r"(r0), "=r"(r1), "=r"(r2), "=r"(r3) : "r"(addr))

#define MMA16816(d, a, b0_, b1_) \
    asm volatile("mma.sync.aligned.m16n8k16.row.col.f32.bf16.bf16.f32 " \
                 "{%0,%1,%2,%3},{%4,%5,%6,%7},{%8,%9},{%0,%1,%2,%3};" \
                 : "+f"((d)[0]), "+f"((d)[1]), "+f"((d)[2]), "+f"((d)[3]) \
                 : "r"((a)[0]), "r"((a)[1]), "r"((a)[2]), "r"((a)[3]), \
                   "r"(b0_), "r"(b1_))

#define CP16(dst, src) \
    asm volatile("cp.async.cg.shared.global [%0], [%1], 16;" \
                 :: "r"(dst), "l"((unsigned long long)__cvta_generic_to_global(src)))

// ---------------------------------------------------------------------------
// Split-bf16 mma.sync GEMM: C[M,N] = A[M,K] * B[N,K]^T (+bias), fp32 out.
// TERMS==3: Ahi*Bhi + Alo*Bhi + Ahi*Blo.  TERMS==2: A*Bhi + A*Blo.
// BM=128, BN=256, BK=32. 256 threads = 8 warps (2x4), warp tile 64x64.
// 3-stage cp.async pipeline. 80B-padded smem rows (conflict-free ldmatrix).
// C row stride = ldc (allows fused RKV output).
// ---------------------------------------------------------------------------
template <int TERMS>
__global__ __launch_bounds__(256, 1)
void mma_gemm(const __nv_bfloat16* __restrict__ Ah, const __nv_bfloat16* __restrict__ Al,
              const __nv_bfloat16* __restrict__ Bh, const __nv_bfloat16* __restrict__ Bl,
              const float* __restrict__ bias, float* __restrict__ C,
              int N, int K, int ldc)
{
    constexpr int S      = 3;
    constexpr int NA     = (TERMS == 3) ? 2 : 1;
    constexpr int MATA   = 128 * 80;              // 10240 B
    constexpr int MATB_B = 256 * 80;              // 20480 B
    constexpr int STAGEB = NA * MATA + 2 * MATB_B;
    constexpr int ACH    = NA * 512;              // A 16B-chunks per stage
    constexpr int NCHUNK = (NA * 512 + 2048) / 256;

    extern __shared__ __align__(16) char smem[];
    const uint32_t sb = smem_u32(smem);

    const int tid  = threadIdx.x;
    const int lane = tid & 31;
    const int warp = tid >> 5;
    const int m0w  = (warp >> 2) * 64;            // 2 warps in M
    const int n0w  = (warp & 3) * 64;             // 4 warps in N
    const int mBlk = blockIdx.y * 128;
    const int nBlk = blockIdx.x * 256;

    // base pointers (rowbase folded in)
    const __nv_bfloat16* pA[2];
    pA[0] = Ah + (size_t)mBlk * K;
    pA[1] = (TERMS == 3) ? (Al + (size_t)mBlk * K) : pA[0];
    const __nv_bfloat16* pB[2];
    pB[0] = Bh + (size_t)nBlk * K;
    pB[1] = Bl + (size_t)nBlk * K;

    const int NT = K / 32;

    // ---- stage loader (addresses constant-fold per unrolled i) ----
    auto loadStage = [&](int kt) {
        uint32_t base = sb + (kt % S) * STAGEB;
        const int kof = kt * 32;
#pragma unroll
        for (int i = 0; i < NCHUNK; i++) {
            int c = i * 256 + tid;
            if (c < ACH) {
                int mat = c >> 9;
                int a   = c & 511;
                int r   = a >> 2;
                int c16 = a & 3;
                CP16(base + mat * MATA + r * 80 + c16 * 16,
                     pA[mat] + (size_t)r * K + kof + c16 * 8);
            } else {
                int cb  = c - ACH;
                int mat = cb >> 10;
                int bq  = cb & 1023;
                int r   = bq >> 2;
                int c16 = bq & 3;
                CP16(base + NA * MATA + mat * MATB_B + r * 80 + c16 * 16,
                     pB[mat] + (size_t)r * K + kof + c16 * 8);
            }
        }
    };

    // prologue
#pragma unroll
    for (int s = 0; s < S - 1; s++) {
        loadStage(s);
        asm volatile("cp.async.commit_group;");
    }

    float acc[4][8][4];
#pragma unroll
    for (int i = 0; i < 4; i++)
#pragma unroll
        for (int j = 0; j < 8; j++)
#pragma unroll
            for (int k = 0; k < 4; k++) acc[i][j][k] = 0.f;

    const uint32_t aoff = (uint32_t)((m0w + (lane & 15)) * 80 + (lane >> 4) * 16);
    const uint32_t boff = (uint32_t)((n0w + ((lane >> 4) & 1) * 8 + (lane & 7)) * 80
                                     + ((lane >> 3) & 1) * 16);
    constexpr uint32_t oAhi = 0;
    constexpr uint32_t oAlo = MATA;
    constexpr uint32_t oBhi = NA * MATA;
    constexpr uint32_t oBlo = NA * MATA + MATB_B;

    for (int kt = 0; kt < NT; kt++) {
        asm volatile("cp.async.wait_group 1;" ::: "memory");
        __syncthreads();
        const uint32_t st = sb + (kt % S) * STAGEB;

#pragma unroll
        for (int kk = 0; kk < 2; kk++) {
            const uint32_t kb = kk * 32;

            uint32_t a4[4][4], b4[4][4], c4[4][4];
#pragma unroll
            for (int mt = 0; mt < 4; mt++)
                LDSM_X4(a4[mt][0], a4[mt][1], a4[mt][2], a4[mt][3],
                        st + oAhi + aoff + mt * 1280 + kb);
#pragma unroll
            for (int q = 0; q < 4; q++)
                LDSM_X4(b4[q][0], b4[q][1], b4[q][2], b4[q][3],
                        st + oBhi + boff + q * 1280 + kb);

            // Ah * Bh
#pragma unroll
            for (int mt = 0; mt < 4; mt++)
#pragma unroll
                for (int q = 0; q < 4; q++) {
                    MMA16816(acc[mt][2 * q],     a4[mt], b4[q][0], b4[q][1]);
                    MMA16816(acc[mt][2 * q + 1], a4[mt], b4[q][2], b4[q][3]);
                }

            // Ah * Bl
#pragma unroll
            for (int q = 0; q < 4; q++)
                LDSM_X4(c4[q][0], c4[q][1], c4[q][2], c4[q][3],
                        st + oBlo + boff + q * 1280 + kb);
#pragma unroll
            for (int mt = 0; mt < 4; mt++)
#pragma unroll
                for (int q = 0; q < 4; q++) {
                    MMA16816(acc[mt][2 * q],     a4[mt], c4[q][0], c4[q][1]);
                    MMA16816(acc[mt][2 * q + 1], a4[mt], c4[q][2], c4[q][3]);
                }

            if (TERMS == 3) {
                // Al * Bh (reuse a4 registers)
#pragma unroll
                for (int mt = 0; mt < 4; mt++)
                    LDSM_X4(a4[mt][0], a4[mt][1], a4[mt][2], a4[mt][3],
                            st + oAlo + aoff + mt * 1280 + kb);
#pragma unroll
                for (int mt = 0; mt < 4; mt++)
#pragma unroll
                    for (int q = 0; q < 4; q++) {
                        MMA16816(acc[mt][2 * q],     a4[mt], b4[q][0], b4[q][1]);
                        MMA16816(acc[mt][2 * q + 1], a4[mt], b4[q][2], b4[q][3]);
                    }
            }
        }
        __syncthreads();

        int nxt = kt + S - 1;
        if (nxt < NT) loadStage(nxt);
        asm volatile("cp.async.commit_group;");
    }

    // epilogue
    const int cbase = nBlk + n0w + 2 * (lane & 3);
    const int rbase = mBlk + m0w + (lane >> 2);
#pragma unroll
    for (int mt = 0; mt < 4; mt++) {
#pragma unroll
        for (int nt = 0; nt < 8; nt++) {
            int col = cbase + nt * 8;
            float b0 = 0.f, b1 = 0.f;
            if (bias) { b0 = bias[col]; b1 = bias[col + 1]; }
            int r0 = rbase + mt * 16;
            float2 v0 = make_float2(acc[mt][nt][0] + b0, acc[mt][nt][1] + b1);
            float2 v1 = make_float2(acc[mt][nt][2] + b0, acc[mt][nt][3] + b1);
            *reinterpret_cast<float2*>(C + (size_t)r0 * ldc + col)       = v0;
            *reinterpret_cast<float2*>(C + (size_t)(r0 + 8) * ldc + col) = v1;
        }
    }
}

// ---------------------------------------------------------------------------
// fp32 -> bf16 hi/lo split
// ---------------------------------------------------------------------------
__global__ void split_k(const float* __restrict__ x, __nv_bfloat16* __restrict__ hi,
                        __nv_bfloat16* __restrict__ lo, int n4)
{
    for (int i = blockIdx.x * blockDim.x + threadIdx.x; i < n4;
         i += gridDim.x * blockDim.x) {
        float4 v = reinterpret_cast<const float4*>(x)[i];
        __nv_bfloat16 h0 = __float2bfloat16(v.x);
        __nv_bfloat16 h1 = __float2bfloat16(v.y);
        __nv_bfloat16 h2 = __float2bfloat16(v.z);
        __nv_bfloat16 h3 = __float2bfloat16(v.w);
        reinterpret_cast<__nv_bfloat162*>(hi)[2 * i]     = __nv_bfloat162(h0, h1);
        reinterpret_cast<__nv_bfloat162*>(hi)[2 * i + 1] = __nv_bfloat162(h2, h3);
        __nv_bfloat16 l0 = __float2bfloat16(v.x - __bfloat162float(h0));
        __nv_bfloat16 l1 = __float2bfloat16(v.y - __bfloat162float(h1));
        __nv_bfloat16 l2 = __float2bfloat16(v.z - __bfloat162float(h2));
        __nv_bfloat16 l3 = __float2bfloat16(v.w - __bfloat162float(h3));
        reinterpret_cast<__nv_bfloat162*>(lo)[2 * i]     = __nv_bfloat162(l0, l1);
        reinterpret_cast<__nv_bfloat162*>(lo)[2 * i + 1] = __nv_bfloat162(l2, l3);
    }
}

// ---------------------------------------------------------------------------
// RWKV attention scan: thread per (b,d), PF=16 prefetch double-buffer.
// Reads fused RKV [M, 3072]; writes y as bf16 hi/lo [M, 1024].
// ---------------------------------------------------------------------------
__global__ void attn_scan(const float* __restrict__ RKV,
                          __nv_bfloat16* __restrict__ Yh, __nv_bfloat16* __restrict__ Yl)
{
    constexpr int PF = 16;
    constexpr int NC = Tz / PF;     // 64 chunks
    int idx = blockIdx.x * blockDim.x + threadIdx.x;
    int b = idx >> 10, d = idx & 1023;
    size_t base  = (size_t)b * Tz * 3072 + d;
    size_t baseY = (size_t)b * Tz * 1024 + d;

    float r0[PF], k0[PF], v0[PF], r1[PF], k1[PF], v1[PF];
    float vr = 0.f, vk = 0.f, vv = 0.f, h = 0.f;

#pragma unroll
    for (int j = 0; j < PF; j++) {
        size_t off = base + (size_t)j * 3072;
        r0[j] = RKV[off]; k0[j] = RKV[off + 1024]; v0[j] = RKV[off + 2048];
    }

#define ATTN_STEP(rb, kb, vb, tt)                                        \
    do {                                                                 \
        _Pragma("unroll")                                                \
        for (int j = 0; j < PF; j++) {                                   \
            vr += (rb[j] - vr) * 0.5f;                                   \
            float rs = (vr >= 1.0f) ? 1.f : 0.f;                         \
            if (rs != 0.f) vr = 0.f;                                     \
            vk += (kb[j] - vk) * 0.5f;                                   \
            float ks = (vk >= 1.0f) ? 1.f : 0.f;                         \
            if (ks != 0.f) vk = 0.f;                                     \
            vv += (vb[j] - vv) * 0.5f;                                   \
            float vs = (vv >= 1.0f) ? 1.f : 0.f;                         \
            if (vs != 0.f) vv = 0.f;                                     \
            h = h * 0.9f + ks * vs;                                      \
            float y = rs * h;                                            \
            __nv_bfloat16 yh = __float2bfloat16(y);                      \
            size_t oy = baseY + (size_t)((tt) + j) * 1024;               \
            Yh[oy] = yh;                                                 \
            Yl[oy] = __float2bfloat16(y - __bfloat162float(yh));         \
        }                                                                \
    } while (0)

    for (int tc = 0; tc < NC; tc += 2) {
        if (tc + 1 < NC) {
#pragma unroll
            for (int j = 0; j < PF; j++) {
                size_t off = base + (size_t)((tc + 1) * PF + j) * 3072;
                r1[j] = RKV[off]; k1[j] = RKV[off + 1024]; v1[j] = RKV[off + 2048];
            }
        }
        ATTN_STEP(r0, k0, v0, tc * PF);
        if (tc + 2 < NC) {
#pragma unroll
            for (int j = 0; j < PF; j++) {
                size_t off = base + (size_t)((tc + 2) * PF + j) * 3072;
                r0[j] = RKV[off]; k0[j] = RKV[off + 1024]; v0[j] = RKV[off + 2048];
            }
        }
        ATTN_STEP(r1, k1, v1, (tc + 1) * PF);
    }
#undef ATTN_STEP
}

// ---------------------------------------------------------------------------
// LIF scans with PF=16 prefetch double-buffer.
// ---------------------------------------------------------------------------
template <bool BF16OUT>
__global__ void lif_scan(const float* __restrict__ X, void* __restrict__ Sout, int width)
{
    constexpr int PF = 16;
    constexpr int NC = Tz / PF;
    int idx = blockIdx.x * blockDim.x + threadIdx.x;
    int b = idx / width;
    int f = idx - b * width;
    size_t base = (size_t)b * Tz * width + f;
    __nv_bfloat16* Sb = (__nv_bfloat16*)Sout;
    float* Sf = (float*)Sout;

    float x0[PF], x1[PF];
    float v = 0.f;
#pragma unroll
    for (int j = 0; j < PF; j++) x0[j] = X[base + (size_t)j * width];

#define LIF_STEP(xb, tt)                                                 \
    do {                                                                 \
        _Pragma("unroll")                                                \
        for (int j = 0; j < PF; j++) {                                   \
            v += (xb[j] - v) * 0.5f;                                     \
            float s = (v >= 1.0f) ? 1.f : 0.f;                           \
            if (s != 0.f) v = 0.f;                                       \
            size_t os = base + (size_t)((tt) + j) * width;               \
            if (BF16OUT) Sb[os] = __float2bfloat16(s);                   \
            else         Sf[os] = s;                                     \
        }                                                                \
    } while (0)

    for (int tc = 0; tc < NC; tc += 2) {
        if (tc + 1 < NC) {
#pragma unroll
            for (int j = 0; j < PF; j++)
                x1[j] = X[base + (size_t)((tc + 1) * PF + j) * width];
        }
        LIF_STEP(x0, tc * PF);
        if (tc + 2 < NC) {
#pragma unroll
            for (int j = 0; j < PF; j++)
                x0[j] = X[base + (size_t)((tc + 2) * PF + j) * width];
        }
        LIF_STEP(x1, (tc + 1) * PF);
    }
#undef LIF_STEP
}

// ---------------------------------------------------------------------------
// fused residual add + LayerNorm (block per row, D=1024, 256 threads)
// ---------------------------------------------------------------------------
template <bool SPLIT>
__global__ void add_ln(const float* __restrict__ A, const float* __restrict__ Bv,
                       const float* __restrict__ g, const float* __restrict__ beta,
                       float* __restrict__ O,
                       __nv_bfloat16* __restrict__ Oh, __nv_bfloat16* __restrict__ Ol)
{
    __shared__ float sm[16];
    int row = blockIdx.x;
    int tid = threadIdx.x;
    size_t base = (size_t)row * Dz;
    int c = tid * 4;

    float4 a = *reinterpret_cast<const float4*>(A  + base + c);
    float4 b = *reinterpret_cast<const float4*>(Bv + base + c);
    float x0 = a.x + b.x, x1 = a.y + b.y, x2 = a.z + b.z, x3 = a.w + b.w;

    float s  = x0 + x1 + x2 + x3;
    float ss = x0 * x0 + x1 * x1 + x2 * x2 + x3 * x3;
#pragma unroll
    for (int o = 16; o > 0; o >>= 1) {
        s  += __shfl_xor_sync(0xFFFFFFFFu, s,  o);
        ss += __shfl_xor_sync(0xFFFFFFFFu, ss, o);
    }
    int wid = tid >> 5, lane = tid & 31;
    if (lane == 0) { sm[wid] = s; sm[wid + 8] = ss; }
    __syncthreads();
    if (wid == 0) {
        float s2  = (lane < 8) ? sm[lane]     : 0.f;
        float ss2 = (lane < 8) ? sm[lane + 8] : 0.f;
#pragma unroll
        for (int o = 4; o > 0; o >>= 1) {
            s2  += __shfl_xor_sync(0xFFFFFFFFu, s2,  o);
            ss2 += __shfl_xor_sync(0xFFFFFFFFu, ss2, o);
        }
        if (lane == 0) { sm[0] = s2; sm[1] = ss2; }
    }
    __syncthreads();

    float mu  = sm[0] * (1.f / 1024.f);
    float var = sm[1] * (1.f / 1024.f) - mu * mu;
    float inv = rsqrtf(var + 1e-5f);

    float4 gg = *reinterpret_cast<const float4*>(g    + c);
    float4 bb = *reinterpret_cast<const float4*>(beta + c);
    float4 o;
    o.x = (x0 - mu) * inv * gg.x + bb.x;
    o.y = (x1 - mu) * inv * gg.y + bb.y;
    o.z = (x2 - mu) * inv * gg.z + bb.z;
    o.w = (x3 - mu) * inv * gg.w + bb.w;
    *reinterpret_cast<float4*>(O + base + c) = o;

    if (SPLIT) {
        __nv_bfloat16 h0 = __float2bfloat16(o.x);
        __nv_bfloat16 h1 = __float2bfloat16(o.y);
        __nv_bfloat16 h2 = __float2bfloat16(o.z);
        __nv_bfloat16 h3 = __float2bfloat16(o.w);
        size_t i2 = (base + c) >> 1;
        reinterpret_cast<__nv_bfloat162*>(Oh)[i2]     = __nv_bfloat162(h0, h1);
        reinterpret_cast<__nv_bfloat162*>(Oh)[i2 + 1] = __nv_bfloat162(h2, h3);
        __nv_bfloat16 l0 = __float2bfloat16(o.x - __bfloat162float(h0));
        __nv_bfloat16 l1 = __float2bfloat16(o.y - __bfloat162float(h1));
        __nv_bfloat16 l2 = __float2bfloat16(o.z - __bfloat162float(h2));
        __nv_bfloat16 l3 = __float2bfloat16(o.w - __bfloat162float(h3));
        reinterpret_cast<__nv_bfloat162*>(Ol)[i2]     = __nv_bfloat162(l0, l1);
        reinterpret_cast<__nv_bfloat162*>(Ol)[i2 + 1] = __nv_bfloat162(l2, l3);
    }
}

// ---------------------------------------------------------------------------
// Host side
// ---------------------------------------------------------------------------
static void launch3(const __nv_bfloat16* Ah, const __nv_bfloat16* Al,
                    const __nv_bfloat16* Bh, const __nv_bfloat16* Bl,
                    const float* bias, float* C, int M, int N, int K, int ldc)
{
    const int SMEM = 3 * (2 * 10240 + 2 * 20480);   // 184320
    cudaFuncSetAttribute(mma_gemm<3>, cudaFuncAttributeMaxDynamicSharedMemorySize, SMEM);
    mma_gemm<3><<<dim3(N / 256, M / 128), 256, SMEM>>>(Ah, Al, Bh, Bl, bias, C, N, K, ldc);
}

static void launch2(const __nv_bfloat16* Ah,
                    const __nv_bfloat16* Bh, const __nv_bfloat16* Bl,
                    const float* bias, float* C, int M, int N, int K, int ldc)
{
    const int SMEM = 3 * (10240 + 2 * 20480);       // 153600
    cudaFuncSetAttribute(mma_gemm<2>, cudaFuncAttributeMaxDynamicSharedMemorySize, SMEM);
    mma_gemm<2><<<dim3(N / 256, M / 128), 256, SMEM>>>(Ah, Ah, Bh, Bl, bias, C, N, K, ldc);
}

extern "C" void kernel_launch(void* const* d_in, const int* in_sizes, int n_in,
                              void* d_out, int out_size)
{
    const float* x    = (const float*)d_in[0];
    const float* Wr   = (const float*)d_in[1];
    const float* Wk   = (const float*)d_in[2];
    const float* Wv   = (const float*)d_in[3];
    const float* Wo   = (const float*)d_in[4];
    const float* W1   = (const float*)d_in[5];
    const float* b1   = (const float*)d_in[6];
    const float* W2   = (const float*)d_in[7];
    const float* b2   = (const float*)d_in[8];
    const float* ln1g = (const float*)d_in[9];
    const float* ln1b = (const float*)d_in[10];
    const float* ln2g = (const float*)d_in[11];
    const float* ln2b = (const float*)d_in[12];
    float* out = (float*)d_out;

    float *pRKV, *pAO, *pX1, *pH1, *pH2, *pFFN;
    __nv_bfloat16 *pxh, *pxl, *pyh, *pyl, *px1h, *px1l, *ps1, *pwh, *pwl;
    cudaGetSymbolAddress((void**)&pRKV, g_RKV);
    cudaGetSymbolAddress((void**)&pAO,  g_AO);
    cudaGetSymbolAddress((void**)&pX1,  g_X1);
    cudaGetSymbolAddress((void**)&pH1,  g_H1);
    cudaGetSymbolAddress((void**)&pH2,  g_H2);
    cudaGetSymbolAddress((void**)&pFFN, g_FFN);
    cudaGetSymbolAddress((void**)&pxh,  g_xh);
    cudaGetSymbolAddress((void**)&pxl,  g_xl);
    cudaGetSymbolAddress((void**)&pyh,  g_yh);
    cudaGetSymbolAddress((void**)&pyl,  g_yl);
    cudaGetSymbolAddress((void**)&px1h, g_x1h);
    cudaGetSymbolAddress((void**)&px1l, g_x1l);
    cudaGetSymbolAddress((void**)&ps1,  g_s1);
    cudaGetSymbolAddress((void**)&pwh,  g_wh);
    cudaGetSymbolAddress((void**)&pwl,  g_wl);

    // 1) splits
    split_k<<<1024, 256>>>(x,  pxh, pxl, (Mz * Dz) / 4);
    split_k<<<512,  256>>>(Wr, pwh + OFF_WR, pwl + OFF_WR, (Dz * Dz) / 4);
    split_k<<<512,  256>>>(Wk, pwh + OFF_WK, pwl + OFF_WK, (Dz * Dz) / 4);
    split_k<<<512,  256>>>(Wv, pwh + OFF_WV, pwl + OFF_WV, (Dz * Dz) / 4);
    split_k<<<512,  256>>>(Wo, pwh + OFF_WO, pwl + OFF_WO, (Dz * Dz) / 4);
    split_k<<<1024, 256>>>(W1, pwh + OFF_W1, pwl + OFF_W1, (Fz * Dz) / 4);
    split_k<<<1024, 256>>>(W2, pwh + OFF_W2, pwl + OFF_W2, (Dz * Fz) / 4);

    // 2) fused R|K|V projection: one GEMM, N=3072 (Wr/Wk/Wv contiguous in g_wh)
    launch3(pxh, pxl, pwh + OFF_WR, pwl + OFF_WR, nullptr, pRKV, Mz, 3 * Dz, Dz, 3 * Dz);

    // 3) RWKV attention scan -> y (bf16 hi/lo)
    attn_scan<<<(Bz * Dz) / 32, 32>>>(pRKV, pyh, pyl);

    // 4) output projection
    launch3(pyh, pyl, pwh + OFF_WO, pwl + OFF_WO, nullptr, pAO, Mz, Dz, Dz, Dz);

    // 5) x1 = LN(x + attn_out), plus bf16 hi/lo
    add_ln<true><<<Mz, 256>>>(x, pAO, ln1g, ln1b, pX1, px1h, px1l);

    // 6) h1 = x1 @ W1^T + b1
    launch3(px1h, px1l, pwh + OFF_W1, pwl + OFF_W1, b1, pH1, Mz, Fz, Dz, Fz);

    // 7) s1 = LIF(h1) (bf16-exact spikes)
    lif_scan<true><<<(Bz * Fz) / 128, 128>>>(pH1, ps1, Fz);

    // 8) h2 = s1 @ W2^T + b2 (2-term)
    launch2(ps1, pwh + OFF_W2, pwl + OFF_W2, b2, pH2, Mz, Dz, Fz, Dz);

    // 9) ffn_out = LIF(h2)
    lif_scan<false><<<(Bz * Dz) / 32, 32>>>(pH2, pFFN, Dz);

    // 10) out = LN(x1 + ffn_out)
    add_ln<false><<<Mz, 256>>>(pX1, pFFN, ln2g, ln2b, out, nullptr, nullptr);
}

// round 5
// speedup vs baseline: 2.8461x; 1.0323x over previous
#include <cuda_runtime.h>
#include <cuda_bf16.h>
#include <cstdint>

#define Bz 8
#define Tz 1024
#define Dz 1024
#define Fz 4096
#define Mz (Bz * Tz)   // 8192

// ---------------------------------------------------------------------------
// Device scratch (no allocations allowed)
// ---------------------------------------------------------------------------
__device__ float g_RKV[(size_t)Mz * 3 * Dz];   // fused R|K|V, row stride 3072
__device__ float g_AO [(size_t)Mz * Dz];
__device__ float g_X1 [(size_t)Mz * Dz];
__device__ float g_H2 [(size_t)Mz * Dz];
__device__ float g_FFN[(size_t)Mz * Dz];
__device__ float g_H1 [(size_t)Mz * Fz];

__device__ __nv_bfloat16 g_xh [(size_t)Mz * Dz];
__device__ __nv_bfloat16 g_xl [(size_t)Mz * Dz];
__device__ __nv_bfloat16 g_yh [(size_t)Mz * Dz];
__device__ __nv_bfloat16 g_yl [(size_t)Mz * Dz];
__device__ __nv_bfloat16 g_x1h[(size_t)Mz * Dz];
__device__ __nv_bfloat16 g_x1l[(size_t)Mz * Dz];
__device__ __nv_bfloat16 g_s1 [(size_t)Mz * Fz];

#define NWELEM (4u * 1048576u + 2u * 4194304u)
__device__ __nv_bfloat16 g_wh[NWELEM];
__device__ __nv_bfloat16 g_wl[NWELEM];

#define OFF_WR 0u
#define OFF_WK 1048576u
#define OFF_WV 2097152u
#define OFF_WO 3145728u
#define OFF_W1 4194304u
#define OFF_W2 8388608u

// ---------------------------------------------------------------------------
// helpers
// ---------------------------------------------------------------------------
__device__ __forceinline__ uint32_t smem_u32(const void* p) {
    uint32_t a;
    asm("{ .reg .u64 t; cvta.to.shared.u64 t, %1; cvt.u32.u64 %0, t; }"
        : "=r"(a) : "l"(p));
    return a;
}

#define LDSM_X4(r0, r1, r2, r3, addr) \
    asm volatile("ldmatrix.sync.aligned.m8n8.x4.shared.b16 {%0,%1,%2,%3}, [%4];" \
                 : "=r"(r0), "=r"(r1), "=r"(r2), "=r"(r3) : "r"(addr))

#define MMA16816(d, a, b0_, b1_) \
    asm volatile("mma.sync.aligned.m16n8k16.row.col.f32.bf16.bf16.f32 " \
                 "{%0,%1,%2,%3},{%4,%5,%6,%7},{%8,%9},{%0,%1,%2,%3};" \
                 : "+f"((d)[0]), "+f"((d)[1]), "+f"((d)[2]), "+f"((d)[3]) \
                 : "r"((a)[0]), "r"((a)[1]), "r"((a)[2]), "r"((a)[3]), \
                   "r"(b0_), "r"(b1_))

#define CP16(dst, src) \
    asm volatile("cp.async.cg.shared.global [%0], [%1], 16;" \
                 :: "r"(dst), "l"((unsigned long long)__cvta_generic_to_global(src)))

// ---------------------------------------------------------------------------
// Split-bf16 mma.sync GEMM: C[M,N] = A[M,K] * B[N,K]^T (+bias), fp32 out.
// TERMS==3: Ahi*Bhi + Alo*Bhi + Ahi*Blo.  TERMS==2: A*Bhi + A*Blo.
// BM=128, BN=256, BK=32. 256 threads = 8 warps (2x4), warp tile 64x64.
// 3-stage cp.async pipeline, single barrier per stage, loads issued
// before the MMA pass (canonical multistage order).
// ---------------------------------------------------------------------------
template <int TERMS>
__global__ __launch_bounds__(256, 1)
void mma_gemm(const __nv_bfloat16* __restrict__ Ah, const __nv_bfloat16* __restrict__ Al,
              const __nv_bfloat16* __restrict__ Bh, const __nv_bfloat16* __restrict__ Bl,
              const float* __restrict__ bias, float* __restrict__ C,
              int N, int K, int ldc)
{
    constexpr int S      = 3;
    constexpr int NA     = (TERMS == 3) ? 2 : 1;
    constexpr int MATA   = 128 * 80;              // 10240 B
    constexpr int MATB_B = 256 * 80;              // 20480 B
    constexpr int STAGEB = NA * MATA + 2 * MATB_B;
    constexpr int ACH    = NA * 512;              // A 16B-chunks per stage
    constexpr int NCHUNK = (NA * 512 + 2048) / 256;

    extern __shared__ __align__(16) char smem[];
    const uint32_t sb = smem_u32(smem);

    const int tid  = threadIdx.x;
    const int lane = tid & 31;
    const int warp = tid >> 5;
    const int m0w  = (warp >> 2) * 64;            // 2 warps in M
    const int n0w  = (warp & 3) * 64;             // 4 warps in N
    const int mBlk = blockIdx.y * 128;
    const int nBlk = blockIdx.x * 256;

    const __nv_bfloat16* pA[2];
    pA[0] = Ah + (size_t)mBlk * K;
    pA[1] = (TERMS == 3) ? (Al + (size_t)mBlk * K) : pA[0];
    const __nv_bfloat16* pB[2];
    pB[0] = Bh + (size_t)nBlk * K;
    pB[1] = Bl + (size_t)nBlk * K;

    const int NT = K / 32;

    auto loadStage = [&](int kt) {
        uint32_t base = sb + (kt % S) * STAGEB;
        const int kof = kt * 32;
#pragma unroll
        for (int i = 0; i < NCHUNK; i++) {
            int c = i * 256 + tid;
            if (c < ACH) {
                int mat = c >> 9;
                int a   = c & 511;
                int r   = a >> 2;
                int c16 = a & 3;
                CP16(base + mat * MATA + r * 80 + c16 * 16,
                     pA[mat] + (size_t)r * K + kof + c16 * 8);
            } else {
                int cb  = c - ACH;
                int mat = cb >> 10;
                int bq  = cb & 1023;
                int r   = bq >> 2;
                int c16 = bq & 3;
                CP16(base + NA * MATA + mat * MATB_B + r * 80 + c16 * 16,
                     pB[mat] + (size_t)r * K + kof + c16 * 8);
            }
        }
    };

    // prologue
#pragma unroll
    for (int s = 0; s < S - 1; s++) {
        loadStage(s);
        asm volatile("cp.async.commit_group;");
    }

    float acc[4][8][4];
#pragma unroll
    for (int i = 0; i < 4; i++)
#pragma unroll
        for (int j = 0; j < 8; j++)
#pragma unroll
            for (int k = 0; k < 4; k++) acc[i][j][k] = 0.f;

    const uint32_t aoff = (uint32_t)((m0w + (lane & 15)) * 80 + (lane >> 4) * 16);
    const uint32_t boff = (uint32_t)((n0w + ((lane >> 4) & 1) * 8 + (lane & 7)) * 80
                                     + ((lane >> 3) & 1) * 16);
    constexpr uint32_t oAhi = 0;
    constexpr uint32_t oAlo = MATA;
    constexpr uint32_t oBhi = NA * MATA;
    constexpr uint32_t oBlo = NA * MATA + MATB_B;

    for (int kt = 0; kt < NT; kt++) {
        asm volatile("cp.async.wait_group 1;" ::: "memory");
        __syncthreads();

        // Issue next stage's async loads BEFORE the MMA pass: the copies
        // overlap the tensor work. Target stage (kt+2)%3 was last READ at
        // kt-1; the barrier above orders all warps past those reads.
        int nxt = kt + S - 1;
        if (nxt < NT) loadStage(nxt);
        asm volatile("cp.async.commit_group;");

        const uint32_t st = sb + (kt % S) * STAGEB;
#pragma unroll
        for (int kk = 0; kk < 2; kk++) {
            const uint32_t kb = kk * 32;

            uint32_t a4[4][4], b4[4][4], c4[4][4];
#pragma unroll
            for (int mt = 0; mt < 4; mt++)
                LDSM_X4(a4[mt][0], a4[mt][1], a4[mt][2], a4[mt][3],
                        st + oAhi + aoff + mt * 1280 + kb);
#pragma unroll
            for (int q = 0; q < 4; q++)
                LDSM_X4(b4[q][0], b4[q][1], b4[q][2], b4[q][3],
                        st + oBhi + boff + q * 1280 + kb);

            // Ah * Bh
#pragma unroll
            for (int mt = 0; mt < 4; mt++)
#pragma unroll
                for (int q = 0; q < 4; q++) {
                    MMA16816(acc[mt][2 * q],     a4[mt], b4[q][0], b4[q][1]);
                    MMA16816(acc[mt][2 * q + 1], a4[mt], b4[q][2], b4[q][3]);
                }

            // Ah * Bl
#pragma unroll
            for (int q = 0; q < 4; q++)
                LDSM_X4(c4[q][0], c4[q][1], c4[q][2], c4[q][3],
                        st + oBlo + boff + q * 1280 + kb);
#pragma unroll
            for (int mt = 0; mt < 4; mt++)
#pragma unroll
                for (int q = 0; q < 4; q++) {
                    MMA16816(acc[mt][2 * q],     a4[mt], c4[q][0], c4[q][1]);
                    MMA16816(acc[mt][2 * q + 1], a4[mt], c4[q][2], c4[q][3]);
                }

            if (TERMS == 3) {
                // Al * Bh (reuse a4 registers)
#pragma unroll
                for (int mt = 0; mt < 4; mt++)
                    LDSM_X4(a4[mt][0], a4[mt][1], a4[mt][2], a4[mt][3],
                            st + oAlo + aoff + mt * 1280 + kb);
#pragma unroll
                for (int mt = 0; mt < 4; mt++)
#pragma unroll
                    for (int q = 0; q < 4; q++) {
                        MMA16816(acc[mt][2 * q],     a4[mt], b4[q][0], b4[q][1]);
                        MMA16816(acc[mt][2 * q + 1], a4[mt], b4[q][2], b4[q][3]);
                    }
            }
        }
    }

    // epilogue
    const int cbase = nBlk + n0w + 2 * (lane & 3);
    const int rbase = mBlk + m0w + (lane >> 2);
#pragma unroll
    for (int mt = 0; mt < 4; mt++) {
#pragma unroll
        for (int nt = 0; nt < 8; nt++) {
            int col = cbase + nt * 8;
            float b0 = 0.f, b1 = 0.f;
            if (bias) { b0 = bias[col]; b1 = bias[col + 1]; }
            int r0 = rbase + mt * 16;
            float2 v0 = make_float2(acc[mt][nt][0] + b0, acc[mt][nt][1] + b1);
            float2 v1 = make_float2(acc[mt][nt][2] + b0, acc[mt][nt][3] + b1);
            *reinterpret_cast<float2*>(C + (size_t)r0 * ldc + col)       = v0;
            *reinterpret_cast<float2*>(C + (size_t)(r0 + 8) * ldc + col) = v1;
        }
    }
}

// ---------------------------------------------------------------------------
// fp32 -> bf16 hi/lo split (one float4 per thread, exact grid — BW bound)
// ---------------------------------------------------------------------------
__global__ void split_k(const float* __restrict__ x, __nv_bfloat16* __restrict__ hi,
                        __nv_bfloat16* __restrict__ lo)
{
    int i = blockIdx.x * blockDim.x + threadIdx.x;
    float4 v = reinterpret_cast<const float4*>(x)[i];
    __nv_bfloat16 h0 = __float2bfloat16(v.x);
    __nv_bfloat16 h1 = __float2bfloat16(v.y);
    __nv_bfloat16 h2 = __float2bfloat16(v.z);
    __nv_bfloat16 h3 = __float2bfloat16(v.w);
    reinterpret_cast<__nv_bfloat162*>(hi)[2 * i]     = __nv_bfloat162(h0, h1);
    reinterpret_cast<__nv_bfloat162*>(hi)[2 * i + 1] = __nv_bfloat162(h2, h3);
    __nv_bfloat16 l0 = __float2bfloat16(v.x - __bfloat162float(h0));
    __nv_bfloat16 l1 = __float2bfloat16(v.y - __bfloat162float(h1));
    __nv_bfloat16 l2 = __float2bfloat16(v.z - __bfloat162float(h2));
    __nv_bfloat16 l3 = __float2bfloat16(v.w - __bfloat162float(h3));
    reinterpret_cast<__nv_bfloat162*>(lo)[2 * i]     = __nv_bfloat162(l0, l1);
    reinterpret_cast<__nv_bfloat162*>(lo)[2 * i + 1] = __nv_bfloat162(l2, l3);
}

// ---------------------------------------------------------------------------
// RWKV attention scan: thread per (b,d), PF=16 prefetch double-buffer.
// ---------------------------------------------------------------------------
__global__ void attn_scan(const float* __restrict__ RKV,
                          __nv_bfloat16* __restrict__ Yh, __nv_bfloat16* __restrict__ Yl)
{
    constexpr int PF = 16;
    constexpr int NC = Tz / PF;
    int idx = blockIdx.x * blockDim.x + threadIdx.x;
    int b = idx >> 10, d = idx & 1023;
    size_t base  = (size_t)b * Tz * 3072 + d;
    size_t baseY = (size_t)b * Tz * 1024 + d;

    float r0[PF], k0[PF], v0[PF], r1[PF], k1[PF], v1[PF];
    float vr = 0.f, vk = 0.f, vv = 0.f, h = 0.f;

#pragma unroll
    for (int j = 0; j < PF; j++) {
        size_t off = base + (size_t)j * 3072;
        r0[j] = RKV[off]; k0[j] = RKV[off + 1024]; v0[j] = RKV[off + 2048];
    }

#define ATTN_STEP(rb, kb, vb, tt)                                        \
    do {                                                                 \
        _Pragma("unroll")                                                \
        for (int j = 0; j < PF; j++) {                                   \
            vr += (rb[j] - vr) * 0.5f;                                   \
            float rs = (vr >= 1.0f) ? 1.f : 0.f;                         \
            if (rs != 0.f) vr = 0.f;                                     \
            vk += (kb[j] - vk) * 0.5f;                                   \
            float ks = (vk >= 1.0f) ? 1.f : 0.f;                         \
            if (ks != 0.f) vk = 0.f;                                     \
            vv += (vb[j] - vv) * 0.5f;                                   \
            float vs = (vv >= 1.0f) ? 1.f : 0.f;                         \
            if (vs != 0.f) vv = 0.f;                                     \
            h = h * 0.9f + ks * vs;                                      \
            float y = rs * h;                                            \
            __nv_bfloat16 yh = __float2bfloat16(y);                      \
            size_t oy = baseY + (size_t)((tt) + j) * 1024;               \
            Yh[oy] = yh;                                                 \
            Yl[oy] = __float2bfloat16(y - __bfloat162float(yh));         \
        }                                                                \
    } while (0)

    for (int tc = 0; tc < NC; tc += 2) {
        if (tc + 1 < NC) {
#pragma unroll
            for (int j = 0; j < PF; j++) {
                size_t off = base + (size_t)((tc + 1) * PF + j) * 3072;
                r1[j] = RKV[off]; k1[j] = RKV[off + 1024]; v1[j] = RKV[off + 2048];
            }
        }
        ATTN_STEP(r0, k0, v0, tc * PF);
        if (tc + 2 < NC) {
#pragma unroll
            for (int j = 0; j < PF; j++) {
                size_t off = base + (size_t)((tc + 2) * PF + j) * 3072;
                r0[j] = RKV[off]; k0[j] = RKV[off + 1024]; v0[j] = RKV[off + 2048];
            }
        }
        ATTN_STEP(r1, k1, v1, (tc + 1) * PF);
    }
#undef ATTN_STEP
}

// ---------------------------------------------------------------------------
// LIF scans with PF=16 prefetch double-buffer.
// ---------------------------------------------------------------------------
template <bool BF16OUT>
__global__ void lif_scan(const float* __restrict__ X, void* __restrict__ Sout, int width)
{
    constexpr int PF = 16;
    constexpr int NC = Tz / PF;
    int idx = blockIdx.x * blockDim.x + threadIdx.x;
    int b = idx / width;
    int f = idx - b * width;
    size_t base = (size_t)b * Tz * width + f;
    __nv_bfloat16* Sb = (__nv_bfloat16*)Sout;
    float* Sf = (float*)Sout;

    float x0[PF], x1[PF];
    float v = 0.f;
#pragma unroll
    for (int j = 0; j < PF; j++) x0[j] = X[base + (size_t)j * width];

#define LIF_STEP(xb, tt)                                                 \
    do {                                                                 \
        _Pragma("unroll")                                                \
        for (int j = 0; j < PF; j++) {                                   \
            v += (xb[j] - v) * 0.5f;                                     \
            float s = (v >= 1.0f) ? 1.f : 0.f;                           \
            if (s != 0.f) v = 0.f;                                       \
            size_t os = base + (size_t)((tt) + j) * width;               \
            if (BF16OUT) Sb[os] = __float2bfloat16(s);                   \
            else         Sf[os] = s;                                     \
        }                                                                \
    } while (0)

    for (int tc = 0; tc < NC; tc += 2) {
        if (tc + 1 < NC) {
#pragma unroll
            for (int j = 0; j < PF; j++)
                x1[j] = X[base + (size_t)((tc + 1) * PF + j) * width];
        }
        LIF_STEP(x0, tc * PF);
        if (tc + 2 < NC) {
#pragma unroll
            for (int j = 0; j < PF; j++)
                x0[j] = X[base + (size_t)((tc + 2) * PF + j) * width];
        }
        LIF_STEP(x1, (tc + 1) * PF);
    }
#undef LIF_STEP
}

// ---------------------------------------------------------------------------
// fused residual add + LayerNorm (block per row, D=1024, 256 threads)
// ---------------------------------------------------------------------------
template <bool SPLIT>
__global__ void add_ln(const float* __restrict__ A, const float* __restrict__ Bv,
                       const float* __restrict__ g, const float* __restrict__ beta,
                       float* __restrict__ O,
                       __nv_bfloat16* __restrict__ Oh, __nv_bfloat16* __restrict__ Ol)
{
    __shared__ float sm[16];
    int row = blockIdx.x;
    int tid = threadIdx.x;
    size_t base = (size_t)row * Dz;
    int c = tid * 4;

    float4 a = *reinterpret_cast<const float4*>(A  + base + c);
    float4 b = *reinterpret_cast<const float4*>(Bv + base + c);
    float x0 = a.x + b.x, x1 = a.y + b.y, x2 = a.z + b.z, x3 = a.w + b.w;

    float s  = x0 + x1 + x2 + x3;
    float ss = x0 * x0 + x1 * x1 + x2 * x2 + x3 * x3;
#pragma unroll
    for (int o = 16; o > 0; o >>= 1) {
        s  += __shfl_xor_sync(0xFFFFFFFFu, s,  o);
        ss += __shfl_xor_sync(0xFFFFFFFFu, ss, o);
    }
    int wid = tid >> 5, lane = tid & 31;
    if (lane == 0) { sm[wid] = s; sm[wid + 8] = ss; }
    __syncthreads();
    if (wid == 0) {
        float s2  = (lane < 8) ? sm[lane]     : 0.f;
        float ss2 = (lane < 8) ? sm[lane + 8] : 0.f;
#pragma unroll
        for (int o = 4; o > 0; o >>= 1) {
            s2  += __shfl_xor_sync(0xFFFFFFFFu, s2,  o);
            ss2 += __shfl_xor_sync(0xFFFFFFFFu, ss2, o);
        }
        if (lane == 0) { sm[0] = s2; sm[1] = ss2; }
    }
    __syncthreads();

    float mu  = sm[0] * (1.f / 1024.f);
    float var = sm[1] * (1.f / 1024.f) - mu * mu;
    float inv = rsqrtf(var + 1e-5f);

    float4 gg = *reinterpret_cast<const float4*>(g    + c);
    float4 bb = *reinterpret_cast<const float4*>(beta + c);
    float4 o;
    o.x = (x0 - mu) * inv * gg.x + bb.x;
    o.y = (x1 - mu) * inv * gg.y + bb.y;
    o.z = (x2 - mu) * inv * gg.z + bb.z;
    o.w = (x3 - mu) * inv * gg.w + bb.w;
    *reinterpret_cast<float4*>(O + base + c) = o;

    if (SPLIT) {
        __nv_bfloat16 h0 = __float2bfloat16(o.x);
        __nv_bfloat16 h1 = __float2bfloat16(o.y);
        __nv_bfloat16 h2 = __float2bfloat16(o.z);
        __nv_bfloat16 h3 = __float2bfloat16(o.w);
        size_t i2 = (base + c) >> 1;
        reinterpret_cast<__nv_bfloat162*>(Oh)[i2]     = __nv_bfloat162(h0, h1);
        reinterpret_cast<__nv_bfloat162*>(Oh)[i2 + 1] = __nv_bfloat162(h2, h3);
        __nv_bfloat16 l0 = __float2bfloat16(o.x - __bfloat162float(h0));
        __nv_bfloat16 l1 = __float2bfloat16(o.y - __bfloat162float(h1));
        __nv_bfloat16 l2 = __float2bfloat16(o.z - __bfloat162float(h2));
        __nv_bfloat16 l3 = __float2bfloat16(o.w - __bfloat162float(h3));
        reinterpret_cast<__nv_bfloat162*>(Ol)[i2]     = __nv_bfloat162(l0, l1);
        reinterpret_cast<__nv_bfloat162*>(Ol)[i2 + 1] = __nv_bfloat162(l2, l3);
    }
}

// ---------------------------------------------------------------------------
// Host side
// ---------------------------------------------------------------------------
static void launch3(const __nv_bfloat16* Ah, const __nv_bfloat16* Al,
                    const __nv_bfloat16* Bh, const __nv_bfloat16* Bl,
                    const float* bias, float* C, int M, int N, int K, int ldc)
{
    const int SMEM = 3 * (2 * 10240 + 2 * 20480);   // 184320
    cudaFuncSetAttribute(mma_gemm<3>, cudaFuncAttributeMaxDynamicSharedMemorySize, SMEM);
    mma_gemm<3><<<dim3(N / 256, M / 128), 256, SMEM>>>(Ah, Al, Bh, Bl, bias, C, N, K, ldc);
}

static void launch2(const __nv_bfloat16* Ah,
                    const __nv_bfloat16* Bh, const __nv_bfloat16* Bl,
                    const float* bias, float* C, int M, int N, int K, int ldc)
{
    const int SMEM = 3 * (10240 + 2 * 20480);       // 153600
    cudaFuncSetAttribute(mma_gemm<2>, cudaFuncAttributeMaxDynamicSharedMemorySize, SMEM);
    mma_gemm<2><<<dim3(N / 256, M / 128), 256, SMEM>>>(Ah, Ah, Bh, Bl, bias, C, N, K, ldc);
}

extern "C" void kernel_launch(void* const* d_in, const int* in_sizes, int n_in,
                              void* d_out, int out_size)
{
    const float* x    = (const float*)d_in[0];
    const float* Wr   = (const float*)d_in[1];
    const float* Wk   = (const float*)d_in[2];
    const float* Wv   = (const float*)d_in[3];
    const float* Wo   = (const float*)d_in[4];
    const float* W1   = (const float*)d_in[5];
    const float* b1   = (const float*)d_in[6];
    const float* W2   = (const float*)d_in[7];
    const float* b2   = (const float*)d_in[8];
    const float* ln1g = (const float*)d_in[9];
    const float* ln1b = (const float*)d_in[10];
    const float* ln2g = (const float*)d_in[11];
    const float* ln2b = (const float*)d_in[12];
    float* out = (float*)d_out;

    float *pRKV, *pAO, *pX1, *pH1, *pH2, *pFFN;
    __nv_bfloat16 *pxh, *pxl, *pyh, *pyl, *px1h, *px1l, *ps1, *pwh, *pwl;
    cudaGetSymbolAddress((void**)&pRKV, g_RKV);
    cudaGetSymbolAddress((void**)&pAO,  g_AO);
    cudaGetSymbolAddress((void**)&pX1,  g_X1);
    cudaGetSymbolAddress((void**)&pH1,  g_H1);
    cudaGetSymbolAddress((void**)&pH2,  g_H2);
    cudaGetSymbolAddress((void**)&pFFN, g_FFN);
    cudaGetSymbolAddress((void**)&pxh,  g_xh);
    cudaGetSymbolAddress((void**)&pxl,  g_xl);
    cudaGetSymbolAddress((void**)&pyh,  g_yh);
    cudaGetSymbolAddress((void**)&pyl,  g_yl);
    cudaGetSymbolAddress((void**)&px1h, g_x1h);
    cudaGetSymbolAddress((void**)&px1l, g_x1l);
    cudaGetSymbolAddress((void**)&ps1,  g_s1);
    cudaGetSymbolAddress((void**)&pwh,  g_wh);
    cudaGetSymbolAddress((void**)&pwl,  g_wl);

    // 1) splits (one float4 per thread, exact grids)
    split_k<<<(Mz * Dz) / 1024, 256>>>(x,  pxh, pxl);
    split_k<<<(Dz * Dz) / 1024, 256>>>(Wr, pwh + OFF_WR, pwl + OFF_WR);
    split_k<<<(Dz * Dz) / 1024, 256>>>(Wk, pwh + OFF_WK, pwl + OFF_WK);
    split_k<<<(Dz * Dz) / 1024, 256>>>(Wv, pwh + OFF_WV, pwl + OFF_WV);
    split_k<<<(Dz * Dz) / 1024, 256>>>(Wo, pwh + OFF_WO, pwl + OFF_WO);
    split_k<<<(Fz * Dz) / 1024, 256>>>(W1, pwh + OFF_W1, pwl + OFF_W1);
    split_k<<<(Dz * Fz) / 1024, 256>>>(W2, pwh + OFF_W2, pwl + OFF_W2);

    // 2) fused R|K|V projection: one GEMM, N=3072
    launch3(pxh, pxl, pwh + OFF_WR, pwl + OFF_WR, nullptr, pRKV, Mz, 3 * Dz, Dz, 3 * Dz);

    // 3) RWKV attention scan -> y (bf16 hi/lo)
    attn_scan<<<(Bz * Dz) / 32, 32>>>(pRKV, pyh, pyl);

    // 4) output projection
    launch3(pyh, pyl, pwh + OFF_WO, pwl + OFF_WO, nullptr, pAO, Mz, Dz, Dz, Dz);

    // 5) x1 = LN(x + attn_out), plus bf16 hi/lo
    add_ln<true><<<Mz, 256>>>(x, pAO, ln1g, ln1b, pX1, px1h, px1l);

    // 6) h1 = x1 @ W1^T + b1
    launch3(px1h, px1l, pwh + OFF_W1, pwl + OFF_W1, b1, pH1, Mz, Fz, Dz, Fz);

    // 7) s1 = LIF(h1) (bf16-exact spikes)
    lif_scan<true><<<(Bz * Fz) / 128, 128>>>(pH1, ps1, Fz);

    // 8) h2 = s1 @ W2^T + b2 (2-term)
    launch2(ps1, pwh + OFF_W2, pwl + OFF_W2, b2, pH2, Mz, Dz, Fz, Dz);

    // 9) ffn_out = LIF(h2)
    lif_scan<false><<<(Bz * Dz) / 32, 32>>>(pH2, pFFN, Dz);

    // 10) out = LN(x1 + ffn_out)
    add_ln<false><<<Mz, 256>>>(pX1, pFFN, ln2g, ln2b, out, nullptr, nullptr);
}

// round 6
// speedup vs baseline: 2.9413x; 1.0334x over previous
#include <cuda_runtime.h>
#include <cuda_bf16.h>
#include <cstdint>

#define Bz 8
#define Tz 1024
#define Dz 1024
#define Fz 4096
#define Mz (Bz * Tz)   // 8192

// ---------------------------------------------------------------------------
// Device scratch (no allocations allowed)
// ---------------------------------------------------------------------------
__device__ float g_RKV[(size_t)Mz * 3 * Dz];   // fused R|K|V, row stride 3072
__device__ float g_AO [(size_t)Mz * Dz];
__device__ float g_X1 [(size_t)Mz * Dz];
__device__ float g_H2 [(size_t)Mz * Dz];
__device__ float g_FFN[(size_t)Mz * Dz];
__device__ float g_H1 [(size_t)Mz * Fz];

__device__ __nv_bfloat16 g_xh [(size_t)Mz * Dz];
__device__ __nv_bfloat16 g_xl [(size_t)Mz * Dz];
__device__ __nv_bfloat16 g_yh [(size_t)Mz * Dz];
__device__ __nv_bfloat16 g_yl [(size_t)Mz * Dz];
__device__ __nv_bfloat16 g_x1h[(size_t)Mz * Dz];
__device__ __nv_bfloat16 g_x1l[(size_t)Mz * Dz];
__device__ __nv_bfloat16 g_s1 [(size_t)Mz * Fz];

#define NWELEM (4u * 1048576u + 2u * 4194304u)
__device__ __nv_bfloat16 g_wh[NWELEM];
__device__ __nv_bfloat16 g_wl[NWELEM];

#define OFF_WR 0u
#define OFF_WK 1048576u
#define OFF_WV 2097152u
#define OFF_WO 3145728u
#define OFF_W1 4194304u
#define OFF_W2 8388608u

// ---------------------------------------------------------------------------
// helpers
// ---------------------------------------------------------------------------
__device__ __forceinline__ uint32_t smem_u32(const void* p) {
    uint32_t a;
    asm("{ .reg .u64 t; cvta.to.shared.u64 t, %1; cvt.u32.u64 %0, t; }"
        : "=r"(a) : "l"(p));
    return a;
}

#define LDSM_X4(r0, r1, r2, r3, addr) \
    asm volatile("ldmatrix.sync.aligned.m8n8.x4.shared.b16 {%0,%1,%2,%3}, [%4];" \
                 : "=r"(r0), "=r"(r1), "=r"(r2), "=r"(r3) : "r"(addr))

#define MMA16816(d, a, b0_, b1_) \
    asm volatile("mma.sync.aligned.m16n8k16.row.col.f32.bf16.bf16.f32 " \
                 "{%0,%1,%2,%3},{%4,%5,%6,%7},{%8,%9},{%0,%1,%2,%3};" \
                 : "+f"((d)[0]), "+f"((d)[1]), "+f"((d)[2]), "+f"((d)[3]) \
                 : "r"((a)[0]), "r"((a)[1]), "r"((a)[2]), "r"((a)[3]), \
                   "r"(b0_), "r"(b1_))

#define CP16(dst, src) \
    asm volatile("cp.async.cg.shared.global [%0], [%1], 16;" \
                 :: "r"(dst), "l"((unsigned long long)__cvta_generic_to_global(src)))

// ---------------------------------------------------------------------------
// Split-bf16 mma.sync GEMM (unchanged from R5 — known good):
// C[M,N] = A[M,K] * B[N,K]^T (+bias), fp32 out.
// ---------------------------------------------------------------------------
template <int TERMS>
__global__ __launch_bounds__(256, 1)
void mma_gemm(const __nv_bfloat16* __restrict__ Ah, const __nv_bfloat16* __restrict__ Al,
              const __nv_bfloat16* __restrict__ Bh, const __nv_bfloat16* __restrict__ Bl,
              const float* __restrict__ bias, float* __restrict__ C,
              int N, int K, int ldc)
{
    constexpr int S      = 3;
    constexpr int NA     = (TERMS == 3) ? 2 : 1;
    constexpr int MATA   = 128 * 80;
    constexpr int MATB_B = 256 * 80;
    constexpr int STAGEB = NA * MATA + 2 * MATB_B;
    constexpr int ACH    = NA * 512;
    constexpr int NCHUNK = (NA * 512 + 2048) / 256;

    extern __shared__ __align__(16) char smem[];
    const uint32_t sb = smem_u32(smem);

    const int tid  = threadIdx.x;
    const int lane = tid & 31;
    const int warp = tid >> 5;
    const int m0w  = (warp >> 2) * 64;
    const int n0w  = (warp & 3) * 64;
    const int mBlk = blockIdx.y * 128;
    const int nBlk = blockIdx.x * 256;

    const __nv_bfloat16* pA[2];
    pA[0] = Ah + (size_t)mBlk * K;
    pA[1] = (TERMS == 3) ? (Al + (size_t)mBlk * K) : pA[0];
    const __nv_bfloat16* pB[2];
    pB[0] = Bh + (size_t)nBlk * K;
    pB[1] = Bl + (size_t)nBlk * K;

    const int NT = K / 32;

    auto loadStage = [&](int kt) {
        uint32_t base = sb + (kt % S) * STAGEB;
        const int kof = kt * 32;
#pragma unroll
        for (int i = 0; i < NCHUNK; i++) {
            int c = i * 256 + tid;
            if (c < ACH) {
                int mat = c >> 9;
                int a   = c & 511;
                int r   = a >> 2;
                int c16 = a & 3;
                CP16(base + mat * MATA + r * 80 + c16 * 16,
                     pA[mat] + (size_t)r * K + kof + c16 * 8);
            } else {
                int cb  = c - ACH;
                int mat = cb >> 10;
                int bq  = cb & 1023;
                int r   = bq >> 2;
                int c16 = bq & 3;
                CP16(base + NA * MATA + mat * MATB_B + r * 80 + c16 * 16,
                     pB[mat] + (size_t)r * K + kof + c16 * 8);
            }
        }
    };

#pragma unroll
    for (int s = 0; s < S - 1; s++) {
        loadStage(s);
        asm volatile("cp.async.commit_group;");
    }

    float acc[4][8][4];
#pragma unroll
    for (int i = 0; i < 4; i++)
#pragma unroll
        for (int j = 0; j < 8; j++)
#pragma unroll
            for (int k = 0; k < 4; k++) acc[i][j][k] = 0.f;

    const uint32_t aoff = (uint32_t)((m0w + (lane & 15)) * 80 + (lane >> 4) * 16);
    const uint32_t boff = (uint32_t)((n0w + ((lane >> 4) & 1) * 8 + (lane & 7)) * 80
                                     + ((lane >> 3) & 1) * 16);
    constexpr uint32_t oAhi = 0;
    constexpr uint32_t oAlo = MATA;
    constexpr uint32_t oBhi = NA * MATA;
    constexpr uint32_t oBlo = NA * MATA + MATB_B;

    for (int kt = 0; kt < NT; kt++) {
        asm volatile("cp.async.wait_group 1;" ::: "memory");
        __syncthreads();

        int nxt = kt + S - 1;
        if (nxt < NT) loadStage(nxt);
        asm volatile("cp.async.commit_group;");

        const uint32_t st = sb + (kt % S) * STAGEB;
#pragma unroll
        for (int kk = 0; kk < 2; kk++) {
            const uint32_t kb = kk * 32;

            uint32_t a4[4][4], b4[4][4], c4[4][4];
#pragma unroll
            for (int mt = 0; mt < 4; mt++)
                LDSM_X4(a4[mt][0], a4[mt][1], a4[mt][2], a4[mt][3],
                        st + oAhi + aoff + mt * 1280 + kb);
#pragma unroll
            for (int q = 0; q < 4; q++)
                LDSM_X4(b4[q][0], b4[q][1], b4[q][2], b4[q][3],
                        st + oBhi + boff + q * 1280 + kb);

#pragma unroll
            for (int mt = 0; mt < 4; mt++)
#pragma unroll
                for (int q = 0; q < 4; q++) {
                    MMA16816(acc[mt][2 * q],     a4[mt], b4[q][0], b4[q][1]);
                    MMA16816(acc[mt][2 * q + 1], a4[mt], b4[q][2], b4[q][3]);
                }

#pragma unroll
            for (int q = 0; q < 4; q++)
                LDSM_X4(c4[q][0], c4[q][1], c4[q][2], c4[q][3],
                        st + oBlo + boff + q * 1280 + kb);
#pragma unroll
            for (int mt = 0; mt < 4; mt++)
#pragma unroll
                for (int q = 0; q < 4; q++) {
                    MMA16816(acc[mt][2 * q],     a4[mt], c4[q][0], c4[q][1]);
                    MMA16816(acc[mt][2 * q + 1], a4[mt], c4[q][2], c4[q][3]);
                }

            if (TERMS == 3) {
#pragma unroll
                for (int mt = 0; mt < 4; mt++)
                    LDSM_X4(a4[mt][0], a4[mt][1], a4[mt][2], a4[mt][3],
                            st + oAlo + aoff + mt * 1280 + kb);
#pragma unroll
                for (int mt = 0; mt < 4; mt++)
#pragma unroll
                    for (int q = 0; q < 4; q++) {
                        MMA16816(acc[mt][2 * q],     a4[mt], b4[q][0], b4[q][1]);
                        MMA16816(acc[mt][2 * q + 1], a4[mt], b4[q][2], b4[q][3]);
                    }
            }
        }
    }

    const int cbase = nBlk + n0w + 2 * (lane & 3);
    const int rbase = mBlk + m0w + (lane >> 2);
#pragma unroll
    for (int mt = 0; mt < 4; mt++) {
#pragma unroll
        for (int nt = 0; nt < 8; nt++) {
            int col = cbase + nt * 8;
            float b0 = 0.f, b1 = 0.f;
            if (bias) { b0 = bias[col]; b1 = bias[col + 1]; }
            int r0 = rbase + mt * 16;
            float2 v0 = make_float2(acc[mt][nt][0] + b0, acc[mt][nt][1] + b1);
            float2 v1 = make_float2(acc[mt][nt][2] + b0, acc[mt][nt][3] + b1);
            *reinterpret_cast<float2*>(C + (size_t)r0 * ldc + col)       = v0;
            *reinterpret_cast<float2*>(C + (size_t)(r0 + 8) * ldc + col) = v1;
        }
    }
}

// ---------------------------------------------------------------------------
// fp32 -> bf16 hi/lo split helpers
// ---------------------------------------------------------------------------
__device__ __forceinline__ void split_store(float4 v, __nv_bfloat16* hi,
                                            __nv_bfloat16* lo, size_t i4)
{
    __nv_bfloat16 h0 = __float2bfloat16(v.x);
    __nv_bfloat16 h1 = __float2bfloat16(v.y);
    __nv_bfloat16 h2 = __float2bfloat16(v.z);
    __nv_bfloat16 h3 = __float2bfloat16(v.w);
    reinterpret_cast<__nv_bfloat162*>(hi)[2 * i4]     = __nv_bfloat162(h0, h1);
    reinterpret_cast<__nv_bfloat162*>(hi)[2 * i4 + 1] = __nv_bfloat162(h2, h3);
    __nv_bfloat16 l0 = __float2bfloat16(v.x - __bfloat162float(h0));
    __nv_bfloat16 l1 = __float2bfloat16(v.y - __bfloat162float(h1));
    __nv_bfloat16 l2 = __float2bfloat16(v.z - __bfloat162float(h2));
    __nv_bfloat16 l3 = __float2bfloat16(v.w - __bfloat162float(h3));
    reinterpret_cast<__nv_bfloat162*>(lo)[2 * i4]     = __nv_bfloat162(l0, l1);
    reinterpret_cast<__nv_bfloat162*>(lo)[2 * i4 + 1] = __nv_bfloat162(l2, l3);
}

__global__ void split_k(const float* __restrict__ x, __nv_bfloat16* __restrict__ hi,
                        __nv_bfloat16* __restrict__ lo)
{
    int i = blockIdx.x * blockDim.x + threadIdx.x;
    split_store(reinterpret_cast<const float4*>(x)[i], hi, lo, i);
}

// All 6 weight matrices in one launch; dst layout [Wr|Wk|Wv|Wo|W1|W2] contiguous.
__global__ void split6(const float* __restrict__ wr, const float* __restrict__ wk,
                       const float* __restrict__ wv, const float* __restrict__ wo,
                       const float* __restrict__ w1, const float* __restrict__ w2,
                       __nv_bfloat16* __restrict__ hi, __nv_bfloat16* __restrict__ lo)
{
    int i = blockIdx.x * blockDim.x + threadIdx.x;   // float4 index 0..3145727
    const float* src;
    int off;
    if (i < 1048576) {
        int seg = i >> 18;
        off = i & 262143;
        src = (seg == 0) ? wr : (seg == 1) ? wk : (seg == 2) ? wv : wo;
    } else {
        int j = i - 1048576;
        off = j & 1048575;
        src = (j >> 20) ? w2 : w1;
    }
    split_store(reinterpret_cast<const float4*>(src)[off], hi, lo, i);
}

// ---------------------------------------------------------------------------
// RWKV attention scan, cp.async smem-pipelined.
// Block = 32 threads = 32 channels of one batch; 4-stage ring of
// 32-timestep chunks (48KB smem). Reads fused RKV [M,3072].
// ---------------------------------------------------------------------------
__global__ __launch_bounds__(32, 4)
void attn_scan_cp(const float* __restrict__ RKV,
                  __nv_bfloat16* __restrict__ Yh, __nv_bfloat16* __restrict__ Yl)
{
    constexpr int CT = 32, ST = 4, NCH = Tz / CT;   // 32 chunks
    __shared__ float sm[ST][CT][3][32];             // 49152 B
    const int tid = threadIdx.x;
    const int b   = blockIdx.x >> 5;
    const int cb  = (blockIdx.x & 31) * 32;
    const float* src = RKV + (size_t)b * Tz * 3072 + cb;
    const size_t baseY = (size_t)b * Tz * 1024 + cb + tid;

    auto issue = [&](int tc) {
        const float* s0 = src + (size_t)tc * CT * 3072;
        uint32_t dst = smem_u32(&sm[tc % ST][0][0][0]);
#pragma unroll
        for (int j = 0; j < 24; j++) {              // 768 chunks / 32 threads
            int c   = j * 32 + tid;
            int t   = c / 24;
            int rem = c - t * 24;
            int m   = rem >> 3;
            int ch4 = rem & 7;
            CP16(dst + (uint32_t)(((t * 3 + m) * 32 + ch4 * 4) * 4),
                 s0 + (size_t)t * 3072 + m * 1024 + ch4 * 4);
        }
    };

#pragma unroll
    for (int s = 0; s < ST - 1; s++) {
        issue(s);
        asm volatile("cp.async.commit_group;");
    }

    float vr = 0.f, vk = 0.f, vv = 0.f, h = 0.f;
    for (int tc = 0; tc < NCH; tc++) {
        if (tc + ST - 1 < NCH) issue(tc + ST - 1);
        asm volatile("cp.async.commit_group;");
        asm volatile("cp.async.wait_group %0;" :: "n"(ST - 1));
        __syncwarp();
        const int s = tc % ST;
#pragma unroll
        for (int t = 0; t < CT; t++) {
            float ri = sm[s][t][0][tid];
            float ki = sm[s][t][1][tid];
            float vi = sm[s][t][2][tid];

            vr += (ri - vr) * 0.5f;
            float rs = (vr >= 1.0f) ? 1.f : 0.f;
            if (rs != 0.f) vr = 0.f;
            vk += (ki - vk) * 0.5f;
            float ks = (vk >= 1.0f) ? 1.f : 0.f;
            if (ks != 0.f) vk = 0.f;
            vv += (vi - vv) * 0.5f;
            float vs = (vv >= 1.0f) ? 1.f : 0.f;
            if (vs != 0.f) vv = 0.f;

            h = h * 0.9f + ks * vs;
            float y = rs * h;
            __nv_bfloat16 yh = __float2bfloat16(y);
            size_t oy = baseY + (size_t)(tc * CT + t) * 1024;
            Yh[oy] = yh;
            Yl[oy] = __float2bfloat16(y - __bfloat162float(yh));
        }
        __syncwarp();
    }
}

// ---------------------------------------------------------------------------
// LIF scan (width 1024), cp.async smem-pipelined (same ring structure).
// ---------------------------------------------------------------------------
__global__ __launch_bounds__(32, 8)
void lif_scan_cp(const float* __restrict__ X, float* __restrict__ S1024)
{
    constexpr int CT = 32, ST = 4, NCH = Tz / CT;
    __shared__ float sm[ST][CT][32];                // 16384 B
    const int tid = threadIdx.x;
    const int b   = blockIdx.x >> 5;
    const int cb  = (blockIdx.x & 31) * 32;
    const float* src = X + (size_t)b * Tz * 1024 + cb;
    const size_t baseS = (size_t)b * Tz * 1024 + cb + tid;

    auto issue = [&](int tc) {
        const float* s0 = src + (size_t)tc * CT * 1024;
        uint32_t dst = smem_u32(&sm[tc % ST][0][0]);
#pragma unroll
        for (int j = 0; j < 8; j++) {               // 256 chunks / 32 threads
            int c   = j * 32 + tid;
            int t   = c >> 3;
            int ch4 = c & 7;
            CP16(dst + (uint32_t)((t * 32 + ch4 * 4) * 4),
                 s0 + (size_t)t * 1024 + ch4 * 4);
        }
    };

#pragma unroll
    for (int s = 0; s < ST - 1; s++) {
        issue(s);
        asm volatile("cp.async.commit_group;");
    }

    float v = 0.f;
    for (int tc = 0; tc < NCH; tc++) {
        if (tc + ST - 1 < NCH) issue(tc + ST - 1);
        asm volatile("cp.async.commit_group;");
        asm volatile("cp.async.wait_group %0;" :: "n"(ST - 1));
        __syncwarp();
        const int s = tc % ST;
#pragma unroll
        for (int t = 0; t < CT; t++) {
            float x = sm[s][t][tid];
            v += (x - v) * 0.5f;
            float sp = (v >= 1.0f) ? 1.f : 0.f;
            if (sp != 0.f) v = 0.f;
            S1024[baseS + (size_t)(tc * CT + t) * 1024] = sp;
        }
        __syncwarp();
    }
}

// ---------------------------------------------------------------------------
// LIF scan for width 4096 (32K threads — register-PF version, BW-bound)
// ---------------------------------------------------------------------------
__global__ void lif_scan_w4096(const float* __restrict__ X, __nv_bfloat16* __restrict__ S)
{
    constexpr int PF = 16;
    constexpr int NC = Tz / PF;
    int idx = blockIdx.x * blockDim.x + threadIdx.x;
    int b = idx >> 12, f = idx & 4095;
    size_t base = (size_t)b * Tz * 4096 + f;

    float x0[PF], x1[PF];
    float v = 0.f;
#pragma unroll
    for (int j = 0; j < PF; j++) x0[j] = X[base + (size_t)j * 4096];

#define LIF_STEP(xb, tt)                                                 \
    do {                                                                 \
        _Pragma("unroll")                                                \
        for (int j = 0; j < PF; j++) {                                   \
            v += (xb[j] - v) * 0.5f;                                     \
            float s = (v >= 1.0f) ? 1.f : 0.f;                           \
            if (s != 0.f) v = 0.f;                                       \
            S[base + (size_t)((tt) + j) * 4096] = __float2bfloat16(s);   \
        }                                                                \
    } while (0)

    for (int tc = 0; tc < NC; tc += 2) {
        if (tc + 1 < NC) {
#pragma unroll
            for (int j = 0; j < PF; j++)
                x1[j] = X[base + (size_t)((tc + 1) * PF + j) * 4096];
        }
        LIF_STEP(x0, tc * PF);
        if (tc + 2 < NC) {
#pragma unroll
            for (int j = 0; j < PF; j++)
                x0[j] = X[base + (size_t)((tc + 2) * PF + j) * 4096];
        }
        LIF_STEP(x1, (tc + 1) * PF);
    }
#undef LIF_STEP
}

// ---------------------------------------------------------------------------
// fused residual add + LayerNorm (block per row, D=1024, 256 threads)
// ---------------------------------------------------------------------------
template <bool SPLIT>
__global__ void add_ln(const float* __restrict__ A, const float* __restrict__ Bv,
                       const float* __restrict__ g, const float* __restrict__ beta,
                       float* __restrict__ O,
                       __nv_bfloat16* __restrict__ Oh, __nv_bfloat16* __restrict__ Ol)
{
    __shared__ float sm[16];
    int row = blockIdx.x;
    int tid = threadIdx.x;
    size_t base = (size_t)row * Dz;
    int c = tid * 4;

    float4 a = *reinterpret_cast<const float4*>(A  + base + c);
    float4 b = *reinterpret_cast<const float4*>(Bv + base + c);
    float x0 = a.x + b.x, x1 = a.y + b.y, x2 = a.z + b.z, x3 = a.w + b.w;

    float s  = x0 + x1 + x2 + x3;
    float ss = x0 * x0 + x1 * x1 + x2 * x2 + x3 * x3;
#pragma unroll
    for (int o = 16; o > 0; o >>= 1) {
        s  += __shfl_xor_sync(0xFFFFFFFFu, s,  o);
        ss += __shfl_xor_sync(0xFFFFFFFFu, ss, o);
    }
    int wid = tid >> 5, lane = tid & 31;
    if (lane == 0) { sm[wid] = s; sm[wid + 8] = ss; }
    __syncthreads();
    if (wid == 0) {
        float s2  = (lane < 8) ? sm[lane]     : 0.f;
        float ss2 = (lane < 8) ? sm[lane + 8] : 0.f;
#pragma unroll
        for (int o = 4; o > 0; o >>= 1) {
            s2  += __shfl_xor_sync(0xFFFFFFFFu, s2,  o);
            ss2 += __shfl_xor_sync(0xFFFFFFFFu, ss2, o);
        }
        if (lane == 0) { sm[0] = s2; sm[1] = ss2; }
    }
    __syncthreads();

    float mu  = sm[0] * (1.f / 1024.f);
    float var = sm[1] * (1.f / 1024.f) - mu * mu;
    float inv = rsqrtf(var + 1e-5f);

    float4 gg = *reinterpret_cast<const float4*>(g    + c);
    float4 bb = *reinterpret_cast<const float4*>(beta + c);
    float4 o;
    o.x = (x0 - mu) * inv * gg.x + bb.x;
    o.y = (x1 - mu) * inv * gg.y + bb.y;
    o.z = (x2 - mu) * inv * gg.z + bb.z;
    o.w = (x3 - mu) * inv * gg.w + bb.w;
    *reinterpret_cast<float4*>(O + base + c) = o;

    if (SPLIT) split_store(o, Oh, Ol, (base + c) >> 2);
}

// ---------------------------------------------------------------------------
// Host side
// ---------------------------------------------------------------------------
static void launch3(const __nv_bfloat16* Ah, const __nv_bfloat16* Al,
                    const __nv_bfloat16* Bh, const __nv_bfloat16* Bl,
                    const float* bias, float* C, int M, int N, int K, int ldc)
{
    const int SMEM = 3 * (2 * 10240 + 2 * 20480);
    cudaFuncSetAttribute(mma_gemm<3>, cudaFuncAttributeMaxDynamicSharedMemorySize, SMEM);
    mma_gemm<3><<<dim3(N / 256, M / 128), 256, SMEM>>>(Ah, Al, Bh, Bl, bias, C, N, K, ldc);
}

static void launch2(const __nv_bfloat16* Ah,
                    const __nv_bfloat16* Bh, const __nv_bfloat16* Bl,
                    const float* bias, float* C, int M, int N, int K, int ldc)
{
    const int SMEM = 3 * (10240 + 2 * 20480);
    cudaFuncSetAttribute(mma_gemm<2>, cudaFuncAttributeMaxDynamicSharedMemorySize, SMEM);
    mma_gemm<2><<<dim3(N / 256, M / 128), 256, SMEM>>>(Ah, Ah, Bh, Bl, bias, C, N, K, ldc);
}

extern "C" void kernel_launch(void* const* d_in, const int* in_sizes, int n_in,
                              void* d_out, int out_size)
{
    const float* x    = (const float*)d_in[0];
    const float* Wr   = (const float*)d_in[1];
    const float* Wk   = (const float*)d_in[2];
    const float* Wv   = (const float*)d_in[3];
    const float* Wo   = (const float*)d_in[4];
    const float* W1   = (const float*)d_in[5];
    const float* b1   = (const float*)d_in[6];
    const float* W2   = (const float*)d_in[7];
    const float* b2   = (const float*)d_in[8];
    const float* ln1g = (const float*)d_in[9];
    const float* ln1b = (const float*)d_in[10];
    const float* ln2g = (const float*)d_in[11];
    const float* ln2b = (const float*)d_in[12];
    float* out = (float*)d_out;

    float *pRKV, *pAO, *pX1, *pH1, *pH2, *pFFN;
    __nv_bfloat16 *pxh, *pxl, *pyh, *pyl, *px1h, *px1l, *ps1, *pwh, *pwl;
    cudaGetSymbolAddress((void**)&pRKV, g_RKV);
    cudaGetSymbolAddress((void**)&pAO,  g_AO);
    cudaGetSymbolAddress((void**)&pX1,  g_X1);
    cudaGetSymbolAddress((void**)&pH1,  g_H1);
    cudaGetSymbolAddress((void**)&pH2,  g_H2);
    cudaGetSymbolAddress((void**)&pFFN, g_FFN);
    cudaGetSymbolAddress((void**)&pxh,  g_xh);
    cudaGetSymbolAddress((void**)&pxl,  g_xl);
    cudaGetSymbolAddress((void**)&pyh,  g_yh);
    cudaGetSymbolAddress((void**)&pyl,  g_yl);
    cudaGetSymbolAddress((void**)&px1h, g_x1h);
    cudaGetSymbolAddress((void**)&px1l, g_x1l);
    cudaGetSymbolAddress((void**)&ps1,  g_s1);
    cudaGetSymbolAddress((void**)&pwh,  g_wh);
    cudaGetSymbolAddress((void**)&pwl,  g_wl);

    // 1) splits: x (1 launch) + all six weights (1 launch)
    split_k<<<(Mz * Dz) / 1024, 256>>>(x, pxh, pxl);
    split6<<<(NWELEM / 4) / 256, 256>>>(Wr, Wk, Wv, Wo, W1, W2, pwh, pwl);

    // 2) fused R|K|V projection: one GEMM, N=3072
    launch3(pxh, pxl, pwh + OFF_WR, pwl + OFF_WR, nullptr, pRKV, Mz, 3 * Dz, Dz, 3 * Dz);

    // 3) RWKV attention scan -> y (bf16 hi/lo), cp.async-pipelined
    attn_scan_cp<<<Bz * 32, 32>>>(pRKV, pyh, pyl);

    // 4) output projection
    launch3(pyh, pyl, pwh + OFF_WO, pwl + OFF_WO, nullptr, pAO, Mz, Dz, Dz, Dz);

    // 5) x1 = LN(x + attn_out), plus bf16 hi/lo
    add_ln<true><<<Mz, 256>>>(x, pAO, ln1g, ln1b, pX1, px1h, px1l);

    // 6) h1 = x1 @ W1^T + b1
    launch3(px1h, px1l, pwh + OFF_W1, pwl + OFF_W1, b1, pH1, Mz, Fz, Dz, Fz);

    // 7) s1 = LIF(h1) (bf16-exact spikes)
    lif_scan_w4096<<<(Bz * Fz) / 128, 128>>>(pH1, ps1);

    // 8) h2 = s1 @ W2^T + b2 (2-term)
    launch2(ps1, pwh + OFF_W2, pwl + OFF_W2, b2, pH2, Mz, Dz, Fz, Dz);

    // 9) ffn_out = LIF(h2), cp.async-pipelined
    lif_scan_cp<<<Bz * 32, 32>>>(pH2, pFFN);

    // 10) out = LN(x1 + ffn_out)
    add_ln<false><<<Mz, 256>>>(pX1, pFFN, ln2g, ln2b, out, nullptr, nullptr);
}

// round 7
// speedup vs baseline: 3.3361x; 1.1342x over previous
#include <cuda_runtime.h>
#include <cuda_bf16.h>
#include <cstdint>

#define Bz 8
#define Tz 1024
#define Dz 1024
#define Fz 4096
#define Mz (Bz * Tz)   // 8192

// ---------------------------------------------------------------------------
// Device scratch (no allocations allowed)
// ---------------------------------------------------------------------------
__device__ float g_RKV[(size_t)Mz * 3 * Dz];   // fused R|K|V, row stride 3072
__device__ float g_AO [(size_t)Mz * Dz];
__device__ float g_X1 [(size_t)Mz * Dz];
__device__ float g_H2 [(size_t)Mz * Dz];
__device__ float g_FFN[(size_t)Mz * Dz];
__device__ float g_H1 [(size_t)Mz * Fz];

__device__ __nv_bfloat16 g_xh [(size_t)Mz * Dz];
__device__ __nv_bfloat16 g_xl [(size_t)Mz * Dz];
__device__ __nv_bfloat16 g_yh [(size_t)Mz * Dz];
__device__ __nv_bfloat16 g_yl [(size_t)Mz * Dz];
__device__ __nv_bfloat16 g_x1h[(size_t)Mz * Dz];
__device__ __nv_bfloat16 g_x1l[(size_t)Mz * Dz];
__device__ __nv_bfloat16 g_s1 [(size_t)Mz * Fz];

#define NWELEM (4u * 1048576u + 2u * 4194304u)
__device__ __nv_bfloat16 g_wh[NWELEM];
__device__ __nv_bfloat16 g_wl[NWELEM];

#define OFF_WR 0u
#define OFF_WK 1048576u
#define OFF_WV 2097152u
#define OFF_WO 3145728u
#define OFF_W1 4194304u
#define OFF_W2 8388608u

// ---------------------------------------------------------------------------
// helpers
// ---------------------------------------------------------------------------
__device__ __forceinline__ uint32_t smem_u32(const void* p) {
    uint32_t a;
    asm("{ .reg .u64 t; cvta.to.shared.u64 t, %1; cvt.u32.u64 %0, t; }"
        : "=r"(a) : "l"(p));
    return a;
}

#define LDSM_X4(r0, r1, r2, r3, addr) \
    asm volatile("ldmatrix.sync.aligned.m8n8.x4.shared.b16 {%0,%1,%2,%3}, [%4];" \
                 : "=r"(r0), "=r"(r1), "=r"(r2), "=r"(r3) : "r"(addr))

#define MMA16816(d, a, b0_, b1_) \
    asm volatile("mma.sync.aligned.m16n8k16.row.col.f32.bf16.bf16.f32 " \
                 "{%0,%1,%2,%3},{%4,%5,%6,%7},{%8,%9},{%0,%1,%2,%3};" \
                 : "+f"((d)[0]), "+f"((d)[1]), "+f"((d)[2]), "+f"((d)[3]) \
                 : "r"((a)[0]), "r"((a)[1]), "r"((a)[2]), "r"((a)[3]), \
                   "r"(b0_), "r"(b1_))

#define CP16(dst, src) \
    asm volatile("cp.async.cg.shared.global [%0], [%1], 16;" \
                 :: "r"(dst), "l"((unsigned long long)__cvta_generic_to_global(src)))

// ---------------------------------------------------------------------------
// Split-bf16 mma.sync GEMM: C[M,N] = A[M,K] * B[N,K]^T (+bias), fp32 out.
// TERMS==3: Ah*Bh + Ah*Bl + Al*Bh.  TERMS==2: A*Bh + A*Bl.
// BM=128, BN=256, BK=32, 8 warps (2x4), warp tile 64x64, 3-stage cp.async.
// kt-loop issue order tuned: LDSM(Ah,Bh,Bl) first, then cp.async for the
// next stage, then MMA batches with LDSM(Al) overlapped under MMA(Ah*Bh).
// ---------------------------------------------------------------------------
template <int TERMS>
__global__ __launch_bounds__(256, 1)
void mma_gemm(const __nv_bfloat16* __restrict__ Ah, const __nv_bfloat16* __restrict__ Al,
              const __nv_bfloat16* __restrict__ Bh, const __nv_bfloat16* __restrict__ Bl,
              const float* __restrict__ bias, float* __restrict__ C,
              int N, int K, int ldc)
{
    constexpr int S      = 3;
    constexpr int NA     = (TERMS == 3) ? 2 : 1;
    constexpr int MATA   = 128 * 80;
    constexpr int MATB_B = 256 * 80;
    constexpr int STAGEB = NA * MATA + 2 * MATB_B;
    constexpr int ACH    = NA * 512;
    constexpr int NCHUNK = (NA * 512 + 2048) / 256;

    extern __shared__ __align__(16) char smem[];
    const uint32_t sb = smem_u32(smem);

    const int tid  = threadIdx.x;
    const int lane = tid & 31;
    const int warp = tid >> 5;
    const int m0w  = (warp >> 2) * 64;
    const int n0w  = (warp & 3) * 64;
    const int mBlk = blockIdx.y * 128;
    const int nBlk = blockIdx.x * 256;

    const __nv_bfloat16* pA[2];
    pA[0] = Ah + (size_t)mBlk * K;
    pA[1] = (TERMS == 3) ? (Al + (size_t)mBlk * K) : pA[0];
    const __nv_bfloat16* pB[2];
    pB[0] = Bh + (size_t)nBlk * K;
    pB[1] = Bl + (size_t)nBlk * K;

    const int NT = K / 32;

    auto loadStage = [&](int kt) {
        uint32_t base = sb + (kt % S) * STAGEB;
        const int kof = kt * 32;
#pragma unroll
        for (int i = 0; i < NCHUNK; i++) {
            int c = i * 256 + tid;
            if (c < ACH) {
                int mat = c >> 9;
                int a   = c & 511;
                int r   = a >> 2;
                int c16 = a & 3;
                CP16(base + mat * MATA + r * 80 + c16 * 16,
                     pA[mat] + (size_t)r * K + kof + c16 * 8);
            } else {
                int cb  = c - ACH;
                int mat = cb >> 10;
                int bq  = cb & 1023;
                int r   = bq >> 2;
                int c16 = bq & 3;
                CP16(base + NA * MATA + mat * MATB_B + r * 80 + c16 * 16,
                     pB[mat] + (size_t)r * K + kof + c16 * 8);
            }
        }
    };

#pragma unroll
    for (int s = 0; s < S - 1; s++) {
        loadStage(s);
        asm volatile("cp.async.commit_group;");
    }

    float acc[4][8][4];
#pragma unroll
    for (int i = 0; i < 4; i++)
#pragma unroll
        for (int j = 0; j < 8; j++)
#pragma unroll
            for (int k = 0; k < 4; k++) acc[i][j][k] = 0.f;

    const uint32_t aoff = (uint32_t)((m0w + (lane & 15)) * 80 + (lane >> 4) * 16);
    const uint32_t boff = (uint32_t)((n0w + ((lane >> 4) & 1) * 8 + (lane & 7)) * 80
                                     + ((lane >> 3) & 1) * 16);
    constexpr uint32_t oAhi = 0;
    constexpr uint32_t oAlo = MATA;
    constexpr uint32_t oBhi = NA * MATA;
    constexpr uint32_t oBlo = NA * MATA + MATB_B;

    for (int kt = 0; kt < NT; kt++) {
        asm volatile("cp.async.wait_group 1;" ::: "memory");
        __syncthreads();
        const uint32_t st = sb + (kt % S) * STAGEB;
        const int nxt = kt + S - 1;

#pragma unroll
        for (int kk = 0; kk < 2; kk++) {
            const uint32_t kb = kk * 32;

            uint32_t a4[4][4], b4[4][4], c4[4][4];
            // Load this kk's Ah, Bh, Bl fragments FIRST (critical path).
#pragma unroll
            for (int mt = 0; mt < 4; mt++)
                LDSM_X4(a4[mt][0], a4[mt][1], a4[mt][2], a4[mt][3],
                        st + oAhi + aoff + mt * 1280 + kb);
#pragma unroll
            for (int q = 0; q < 4; q++)
                LDSM_X4(b4[q][0], b4[q][1], b4[q][2], b4[q][3],
                        st + oBhi + boff + q * 1280 + kb);
#pragma unroll
            for (int q = 0; q < 4; q++)
                LDSM_X4(c4[q][0], c4[q][1], c4[q][2], c4[q][3],
                        st + oBlo + boff + q * 1280 + kb);

            // Next stage's async copies issue AFTER the fragment loads —
            // they no longer delay the first MMA batch.
            if (kk == 0) {
                if (nxt < NT) loadStage(nxt);
                asm volatile("cp.async.commit_group;");
            }

            // Ah * Bh
#pragma unroll
            for (int mt = 0; mt < 4; mt++)
#pragma unroll
                for (int q = 0; q < 4; q++) {
                    MMA16816(acc[mt][2 * q],     a4[mt], b4[q][0], b4[q][1]);
                    MMA16816(acc[mt][2 * q + 1], a4[mt], b4[q][2], b4[q][3]);
                }

            if (TERMS == 3) {
                // Al loads overlap the Ah*Bh MMA batch above.
                uint32_t d4[4][4];
#pragma unroll
                for (int mt = 0; mt < 4; mt++)
                    LDSM_X4(d4[mt][0], d4[mt][1], d4[mt][2], d4[mt][3],
                            st + oAlo + aoff + mt * 1280 + kb);
                // Ah * Bl
#pragma unroll
                for (int mt = 0; mt < 4; mt++)
#pragma unroll
                    for (int q = 0; q < 4; q++) {
                        MMA16816(acc[mt][2 * q],     a4[mt], c4[q][0], c4[q][1]);
                        MMA16816(acc[mt][2 * q + 1], a4[mt], c4[q][2], c4[q][3]);
                    }
                // Al * Bh
#pragma unroll
                for (int mt = 0; mt < 4; mt++)
#pragma unroll
                    for (int q = 0; q < 4; q++) {
                        MMA16816(acc[mt][2 * q],     d4[mt], b4[q][0], b4[q][1]);
                        MMA16816(acc[mt][2 * q + 1], d4[mt], b4[q][2], b4[q][3]);
                    }
            } else {
                // Ah * Bl
#pragma unroll
                for (int mt = 0; mt < 4; mt++)
#pragma unroll
                    for (int q = 0; q < 4; q++) {
                        MMA16816(acc[mt][2 * q],     a4[mt], c4[q][0], c4[q][1]);
                        MMA16816(acc[mt][2 * q + 1], a4[mt], c4[q][2], c4[q][3]);
                    }
            }
        }
    }

    const int cbase = nBlk + n0w + 2 * (lane & 3);
    const int rbase = mBlk + m0w + (lane >> 2);
#pragma unroll
    for (int mt = 0; mt < 4; mt++) {
#pragma unroll
        for (int nt = 0; nt < 8; nt++) {
            int col = cbase + nt * 8;
            float b0 = 0.f, b1 = 0.f;
            if (bias) { b0 = bias[col]; b1 = bias[col + 1]; }
            int r0 = rbase + mt * 16;
            float2 v0 = make_float2(acc[mt][nt][0] + b0, acc[mt][nt][1] + b1);
            float2 v1 = make_float2(acc[mt][nt][2] + b0, acc[mt][nt][3] + b1);
            *reinterpret_cast<float2*>(C + (size_t)r0 * ldc + col)       = v0;
            *reinterpret_cast<float2*>(C + (size_t)(r0 + 8) * ldc + col) = v1;
        }
    }
}

// ---------------------------------------------------------------------------
// fp32 -> bf16 hi/lo split helpers
// ---------------------------------------------------------------------------
__device__ __forceinline__ void split_store(float4 v, __nv_bfloat16* hi,
                                            __nv_bfloat16* lo, size_t i4)
{
    __nv_bfloat16 h0 = __float2bfloat16(v.x);
    __nv_bfloat16 h1 = __float2bfloat16(v.y);
    __nv_bfloat16 h2 = __float2bfloat16(v.z);
    __nv_bfloat16 h3 = __float2bfloat16(v.w);
    reinterpret_cast<__nv_bfloat162*>(hi)[2 * i4]     = __nv_bfloat162(h0, h1);
    reinterpret_cast<__nv_bfloat162*>(hi)[2 * i4 + 1] = __nv_bfloat162(h2, h3);
    __nv_bfloat16 l0 = __float2bfloat16(v.x - __bfloat162float(h0));
    __nv_bfloat16 l1 = __float2bfloat16(v.y - __bfloat162float(h1));
    __nv_bfloat16 l2 = __float2bfloat16(v.z - __bfloat162float(h2));
    __nv_bfloat16 l3 = __float2bfloat16(v.w - __bfloat162float(h3));
    reinterpret_cast<__nv_bfloat162*>(lo)[2 * i4]     = __nv_bfloat162(l0, l1);
    reinterpret_cast<__nv_bfloat162*>(lo)[2 * i4 + 1] = __nv_bfloat162(l2, l3);
}

__global__ void split_k(const float* __restrict__ x, __nv_bfloat16* __restrict__ hi,
                        __nv_bfloat16* __restrict__ lo)
{
    int i = blockIdx.x * blockDim.x + threadIdx.x;
    split_store(reinterpret_cast<const float4*>(x)[i], hi, lo, i);
}

__global__ void split6(const float* __restrict__ wr, const float* __restrict__ wk,
                       const float* __restrict__ wv, const float* __restrict__ wo,
                       const float* __restrict__ w1, const float* __restrict__ w2,
                       __nv_bfloat16* __restrict__ hi, __nv_bfloat16* __restrict__ lo)
{
    int i = blockIdx.x * blockDim.x + threadIdx.x;
    const float* src;
    int off;
    if (i < 1048576) {
        int seg = i >> 18;
        off = i & 262143;
        src = (seg == 0) ? wr : (seg == 1) ? wk : (seg == 2) ? wv : wo;
    } else {
        int j = i - 1048576;
        off = j & 1048575;
        src = (j >> 20) ? w2 : w1;
    }
    split_store(reinterpret_cast<const float4*>(src)[off], hi, lo, i);
}

// ---------------------------------------------------------------------------
// RWKV attention scan, cp.async smem-pipelined (R6 — measured 3.9TB/s).
// ---------------------------------------------------------------------------
__global__ __launch_bounds__(32, 4)
void attn_scan_cp(const float* __restrict__ RKV,
                  __nv_bfloat16* __restrict__ Yh, __nv_bfloat16* __restrict__ Yl)
{
    constexpr int CT = 32, ST = 4, NCH = Tz / CT;
    __shared__ float sm[ST][CT][3][32];
    const int tid = threadIdx.x;
    const int b   = blockIdx.x >> 5;
    const int cb  = (blockIdx.x & 31) * 32;
    const float* src = RKV + (size_t)b * Tz * 3072 + cb;
    const size_t baseY = (size_t)b * Tz * 1024 + cb + tid;

    auto issue = [&](int tc) {
        const float* s0 = src + (size_t)tc * CT * 3072;
        uint32_t dst = smem_u32(&sm[tc % ST][0][0][0]);
#pragma unroll
        for (int j = 0; j < 24; j++) {
            int c   = j * 32 + tid;
            int t   = c / 24;
            int rem = c - t * 24;
            int m   = rem >> 3;
            int ch4 = rem & 7;
            CP16(dst + (uint32_t)(((t * 3 + m) * 32 + ch4 * 4) * 4),
                 s0 + (size_t)t * 3072 + m * 1024 + ch4 * 4);
        }
    };

#pragma unroll
    for (int s = 0; s < ST - 1; s++) {
        issue(s);
        asm volatile("cp.async.commit_group;");
    }

    float vr = 0.f, vk = 0.f, vv = 0.f, h = 0.f;
    for (int tc = 0; tc < NCH; tc++) {
        if (tc + ST - 1 < NCH) issue(tc + ST - 1);
        asm volatile("cp.async.commit_group;");
        asm volatile("cp.async.wait_group %0;" :: "n"(ST - 1));
        __syncwarp();
        const int s = tc % ST;
#pragma unroll
        for (int t = 0; t < CT; t++) {
            float ri = sm[s][t][0][tid];
            float ki = sm[s][t][1][tid];
            float vi = sm[s][t][2][tid];

            vr += (ri - vr) * 0.5f;
            float rs = (vr >= 1.0f) ? 1.f : 0.f;
            if (rs != 0.f) vr = 0.f;
            vk += (ki - vk) * 0.5f;
            float ks = (vk >= 1.0f) ? 1.f : 0.f;
            if (ks != 0.f) vk = 0.f;
            vv += (vi - vv) * 0.5f;
            float vs = (vv >= 1.0f) ? 1.f : 0.f;
            if (vs != 0.f) vv = 0.f;

            h = h * 0.9f + ks * vs;
            float y = rs * h;
            __nv_bfloat16 yh = __float2bfloat16(y);
            size_t oy = baseY + (size_t)(tc * CT + t) * 1024;
            Yh[oy] = yh;
            Yl[oy] = __float2bfloat16(y - __bfloat162float(yh));
        }
        __syncwarp();
    }
}

// ---------------------------------------------------------------------------
// LIF scan (any width multiple of 32), cp.async smem-pipelined.
// ---------------------------------------------------------------------------
template <bool BF16OUT>
__global__ __launch_bounds__(32, 8)
void lif_scan_cp(const float* __restrict__ X, void* __restrict__ Sout, int width)
{
    constexpr int CT = 32, ST = 4, NCH = Tz / CT;
    __shared__ float sm[ST][CT][32];
    const int tid = threadIdx.x;
    const int gpb = width >> 5;                    // channel-groups per batch
    const int b   = blockIdx.x / gpb;
    const int cb  = (blockIdx.x - b * gpb) * 32;
    const float* src = X + (size_t)b * Tz * width + cb;
    const size_t baseS = (size_t)b * Tz * width + cb + tid;
    __nv_bfloat16* Sb = (__nv_bfloat16*)Sout;
    float* Sf = (float*)Sout;

    auto issue = [&](int tc) {
        const float* s0 = src + (size_t)tc * CT * width;
        uint32_t dst = smem_u32(&sm[tc % ST][0][0]);
#pragma unroll
        for (int j = 0; j < 8; j++) {
            int c   = j * 32 + tid;
            int t   = c >> 3;
            int ch4 = c & 7;
            CP16(dst + (uint32_t)((t * 32 + ch4 * 4) * 4),
                 s0 + (size_t)t * width + ch4 * 4);
        }
    };

#pragma unroll
    for (int s = 0; s < ST - 1; s++) {
        issue(s);
        asm volatile("cp.async.commit_group;");
    }

    float v = 0.f;
    for (int tc = 0; tc < NCH; tc++) {
        if (tc + ST - 1 < NCH) issue(tc + ST - 1);
        asm volatile("cp.async.commit_group;");
        asm volatile("cp.async.wait_group %0;" :: "n"(ST - 1));
        __syncwarp();
        const int s = tc % ST;
#pragma unroll
        for (int t = 0; t < CT; t++) {
            float x = sm[s][t][tid];
            v += (x - v) * 0.5f;
            float sp = (v >= 1.0f) ? 1.f : 0.f;
            if (sp != 0.f) v = 0.f;
            size_t os = baseS + (size_t)(tc * CT + t) * width;
            if (BF16OUT) Sb[os] = __float2bfloat16(sp);
            else         Sf[os] = sp;
        }
        __syncwarp();
    }
}

// ---------------------------------------------------------------------------
// fused residual add + LayerNorm (block per row, D=1024, 256 threads)
// ---------------------------------------------------------------------------
template <bool SPLIT>
__global__ void add_ln(const float* __restrict__ A, const float* __restrict__ Bv,
                       const float* __restrict__ g, const float* __restrict__ beta,
                       float* __restrict__ O,
                       __nv_bfloat16* __restrict__ Oh, __nv_bfloat16* __restrict__ Ol)
{
    __shared__ float sm[16];
    int row = blockIdx.x;
    int tid = threadIdx.x;
    size_t base = (size_t)row * Dz;
    int c = tid * 4;

    float4 a = *reinterpret_cast<const float4*>(A  + base + c);
    float4 b = *reinterpret_cast<const float4*>(Bv + base + c);
    float x0 = a.x + b.x, x1 = a.y + b.y, x2 = a.z + b.z, x3 = a.w + b.w;

    float s  = x0 + x1 + x2 + x3;
    float ss = x0 * x0 + x1 * x1 + x2 * x2 + x3 * x3;
#pragma unroll
    for (int o = 16; o > 0; o >>= 1) {
        s  += __shfl_xor_sync(0xFFFFFFFFu, s,  o);
        ss += __shfl_xor_sync(0xFFFFFFFFu, ss, o);
    }
    int wid = tid >> 5, lane = tid & 31;
    if (lane == 0) { sm[wid] = s; sm[wid + 8] = ss; }
    __syncthreads();
    if (wid == 0) {
        float s2  = (lane < 8) ? sm[lane]     : 0.f;
        float ss2 = (lane < 8) ? sm[lane + 8] : 0.f;
#pragma unroll
        for (int o = 4; o > 0; o >>= 1) {
            s2  += __shfl_xor_sync(0xFFFFFFFFu, s2,  o);
            ss2 += __shfl_xor_sync(0xFFFFFFFFu, ss2, o);
        }
        if (lane == 0) { sm[0] = s2; sm[1] = ss2; }
    }
    __syncthreads();

    float mu  = sm[0] * (1.f / 1024.f);
    float var = sm[1] * (1.f / 1024.f) - mu * mu;
    float inv = rsqrtf(var + 1e-5f);

    float4 gg = *reinterpret_cast<const float4*>(g    + c);
    float4 bb = *reinterpret_cast<const float4*>(beta + c);
    float4 o;
    o.x = (x0 - mu) * inv * gg.x + bb.x;
    o.y = (x1 - mu) * inv * gg.y + bb.y;
    o.z = (x2 - mu) * inv * gg.z + bb.z;
    o.w = (x3 - mu) * inv * gg.w + bb.w;
    *reinterpret_cast<float4*>(O + base + c) = o;

    if (SPLIT) split_store(o, Oh, Ol, (base + c) >> 2);
}

// ---------------------------------------------------------------------------
// Host side
// ---------------------------------------------------------------------------
static void launch3(const __nv_bfloat16* Ah, const __nv_bfloat16* Al,
                    const __nv_bfloat16* Bh, const __nv_bfloat16* Bl,
                    const float* bias, float* C, int M, int N, int K, int ldc)
{
    const int SMEM = 3 * (2 * 10240 + 2 * 20480);
    cudaFuncSetAttribute(mma_gemm<3>, cudaFuncAttributeMaxDynamicSharedMemorySize, SMEM);
    mma_gemm<3><<<dim3(N / 256, M / 128), 256, SMEM>>>(Ah, Al, Bh, Bl, bias, C, N, K, ldc);
}

static void launch2(const __nv_bfloat16* Ah,
                    const __nv_bfloat16* Bh, const __nv_bfloat16* Bl,
                    const float* bias, float* C, int M, int N, int K, int ldc)
{
    const int SMEM = 3 * (10240 + 2 * 20480);
    cudaFuncSetAttribute(mma_gemm<2>, cudaFuncAttributeMaxDynamicSharedMemorySize, SMEM);
    mma_gemm<2><<<dim3(N / 256, M / 128), 256, SMEM>>>(Ah, Ah, Bh, Bl, bias, C, N, K, ldc);
}

extern "C" void kernel_launch(void* const* d_in, const int* in_sizes, int n_in,
                              void* d_out, int out_size)
{
    const float* x    = (const float*)d_in[0];
    const float* Wr   = (const float*)d_in[1];
    const float* Wk   = (const float*)d_in[2];
    const float* Wv   = (const float*)d_in[3];
    const float* Wo   = (const float*)d_in[4];
    const float* W1   = (const float*)d_in[5];
    const float* b1   = (const float*)d_in[6];
    const float* W2   = (const float*)d_in[7];
    const float* b2   = (const float*)d_in[8];
    const float* ln1g = (const float*)d_in[9];
    const float* ln1b = (const float*)d_in[10];
    const float* ln2g = (const float*)d_in[11];
    const float* ln2b = (const float*)d_in[12];
    float* out = (float*)d_out;

    float *pRKV, *pAO, *pX1, *pH1, *pH2, *pFFN;
    __nv_bfloat16 *pxh, *pxl, *pyh, *pyl, *px1h, *px1l, *ps1, *pwh, *pwl;
    cudaGetSymbolAddress((void**)&pRKV, g_RKV);
    cudaGetSymbolAddress((void**)&pAO,  g_AO);
    cudaGetSymbolAddress((void**)&pX1,  g_X1);
    cudaGetSymbolAddress((void**)&pH1,  g_H1);
    cudaGetSymbolAddress((void**)&pH2,  g_H2);
    cudaGetSymbolAddress((void**)&pFFN, g_FFN);
    cudaGetSymbolAddress((void**)&pxh,  g_xh);
    cudaGetSymbolAddress((void**)&pxl,  g_xl);
    cudaGetSymbolAddress((void**)&pyh,  g_yh);
    cudaGetSymbolAddress((void**)&pyl,  g_yl);
    cudaGetSymbolAddress((void**)&px1h, g_x1h);
    cudaGetSymbolAddress((void**)&px1l, g_x1l);
    cudaGetSymbolAddress((void**)&ps1,  g_s1);
    cudaGetSymbolAddress((void**)&pwh,  g_wh);
    cudaGetSymbolAddress((void**)&pwl,  g_wl);

    // 1) splits
    split_k<<<(Mz * Dz) / 1024, 256>>>(x, pxh, pxl);
    split6<<<(NWELEM / 4) / 256, 256>>>(Wr, Wk, Wv, Wo, W1, W2, pwh, pwl);

    // 2) fused R|K|V projection: one GEMM, N=3072
    launch3(pxh, pxl, pwh + OFF_WR, pwl + OFF_WR, nullptr, pRKV, Mz, 3 * Dz, Dz, 3 * Dz);

    // 3) RWKV attention scan -> y (bf16 hi/lo)
    attn_scan_cp<<<Bz * 32, 32>>>(pRKV, pyh, pyl);

    // 4) output projection
    launch3(pyh, pyl, pwh + OFF_WO, pwl + OFF_WO, nullptr, pAO, Mz, Dz, Dz, Dz);

    // 5) x1 = LN(x + attn_out), plus bf16 hi/lo
    add_ln<true><<<Mz, 256>>>(x, pAO, ln1g, ln1b, pX1, px1h, px1l);

    // 6) h1 = x1 @ W1^T + b1
    launch3(px1h, px1l, pwh + OFF_W1, pwl + OFF_W1, b1, pH1, Mz, Fz, Dz, Fz);

    // 7) s1 = LIF(h1) (bf16-exact spikes), cp.async-pipelined
    lif_scan_cp<true><<<Bz * (Fz / 32), 32>>>(pH1, ps1, Fz);

    // 8) h2 = s1 @ W2^T + b2 (2-term)
    launch2(ps1, pwh + OFF_W2, pwl + OFF_W2, b2, pH2, Mz, Dz, Fz, Dz);

    // 9) ffn_out = LIF(h2), cp.async-pipelined
    lif_scan_cp<false><<<Bz * (Dz / 32), 32>>>(pH2, pFFN, Dz);

    // 10) out = LN(x1 + ffn_out)
    add_ln<false><<<Mz, 256>>>(pX1, pFFN, ln2g, ln2b, out, nullptr, nullptr);
}